// round 2
// baseline (speedup 1.0000x reference)
#include <cuda_runtime.h>
#include <cuda_bf16.h>
#include <math.h>

// Problem dims
#define BB 2048
#define SS 128
#define VV 128
#define EE 300
#define HH 512
#define GIN_W (HH + EE)      // 812
#define H3 (3 * HH)          // 1536
#define MROWS (BB * SS)      // 262144

// ---------------- scratch (device globals; no allocation allowed) ----------------
__device__ float g_u[BB * HH];          // h0 @ W2^T + W2_b
__device__ float g_gh[BB * H3];         // h0 @ gru_w_hh^T + gru_b_hh
__device__ float g_logits[BB * SS];     // attention logits
__device__ float g_gin[BB * GIN_W];     // [ctx | emb]
__device__ float g_gi[BB * H3];         // gin @ gru_w_ih^T + gru_b_ih
__device__ float g_hnew[BB * HH];
__device__ float g_a1[BB * EE];         // leaky_relu(fc1)

// ---------------- generic tiled SGEMM: C[M,N] = A[M,K] @ B[N,K]^T + bias ----------------
// 64x64 tile, 256 threads, 4x4 per thread. ACT: 0=none, 1=leaky_relu(0.01)
template<int ACT>
__global__ void __launch_bounds__(256) sgemm_bt(
    const float* __restrict__ A, const float* __restrict__ Bm,
    const float* __restrict__ bias, float* __restrict__ C,
    int M, int N, int K)
{
    __shared__ float As[16][65];   // As[k][m]
    __shared__ float Bs[16][65];   // Bs[k][n]
    const int tid = threadIdx.x;
    const int tx = tid & 15, ty = tid >> 4;
    const int m0 = blockIdx.y * 64, n0 = blockIdx.x * 64;

    float acc[4][4] = {};
    for (int k0 = 0; k0 < K; k0 += 16) {
        #pragma unroll
        for (int r = 0; r < 4; r++) {
            int i = tid + r * 256;
            int m = i >> 4, k = i & 15;
            float v = 0.f;
            if (m0 + m < M && k0 + k < K) v = A[(size_t)(m0 + m) * K + k0 + k];
            As[k][m] = v;
        }
        #pragma unroll
        for (int r = 0; r < 4; r++) {
            int i = tid + r * 256;
            int n = i >> 4, k = i & 15;
            float v = 0.f;
            if (n0 + n < N && k0 + k < K) v = Bm[(size_t)(n0 + n) * K + k0 + k];
            Bs[k][n] = v;
        }
        __syncthreads();
        #pragma unroll
        for (int kk = 0; kk < 16; kk++) {
            float a[4], b[4];
            #pragma unroll
            for (int i = 0; i < 4; i++) a[i] = As[kk][ty * 4 + i];
            #pragma unroll
            for (int j = 0; j < 4; j++) b[j] = Bs[kk][tx * 4 + j];
            #pragma unroll
            for (int i = 0; i < 4; i++)
                #pragma unroll
                for (int j = 0; j < 4; j++)
                    acc[i][j] += a[i] * b[j];
        }
        __syncthreads();
    }
    #pragma unroll
    for (int i = 0; i < 4; i++) {
        int m = m0 + ty * 4 + i;
        if (m >= M) break;
        #pragma unroll
        for (int j = 0; j < 4; j++) {
            int n = n0 + tx * 4 + j;
            if (n < N) {
                float v = acc[i][j] + (bias ? bias[n] : 0.f);
                if (ACT == 1) v = (v > 0.f) ? v : 0.01f * v;
                C[(size_t)m * N + n] = v;
            }
        }
    }
}

// ---------------- fused attention logits ----------------
// logits[m] = V_b + sum_n Vw[n] * tanh( enc_row[m] . W1[n] + W1_b[n] + u[b][n] )
// Block: 64 rows (one b per block since 64 | S=128). A-slab (64x512) cached in smem,
// swept against all 8 N-tiles; W1 stays L2-resident.
#define APAD 524
__global__ void __launch_bounds__(256) attn_logits(
    const float* __restrict__ enc, const float* __restrict__ W1,
    const float* __restrict__ W1b, const float* __restrict__ u,
    const float* __restrict__ Vw, const float* __restrict__ Vb,
    float* __restrict__ logits)
{
    extern __shared__ float sm[];
    float* As = sm;                 // [64][APAD]
    float* Bs = As + 64 * APAD;     // [16][68]
    const int tid = threadIdx.x;
    const int tx = tid & 15, ty = tid >> 4;
    const int m0 = blockIdx.x * 64;
    const int b  = m0 / SS;

    // load 64x512 A slab (float4, coalesced)
    const float4* encv = (const float4*)(enc + (size_t)m0 * HH);
    for (int i = tid; i < 64 * (HH / 4); i += 256) {
        int m = i >> 7;            // 128 float4 per row
        int c4 = i & 127;
        float4 v = encv[m * 128 + c4];
        float* dst = As + m * APAD + c4 * 4;
        dst[0] = v.x; dst[1] = v.y; dst[2] = v.z; dst[3] = v.w;
    }
    __syncthreads();

    float rpart[4] = {0.f, 0.f, 0.f, 0.f};
    const float* urow = u + (size_t)b * HH;

    for (int nt = 0; nt < 8; nt++) {
        const int n0 = nt * 64;
        float acc[4][4] = {};
        for (int k0 = 0; k0 < HH; k0 += 16) {
            // load W1 tile: Bs[k][n] = W1[n0+n][k0+k]
            #pragma unroll
            for (int r = 0; r < 4; r++) {
                int i = tid + r * 256;
                int n = i >> 4, k = i & 15;
                Bs[k * 68 + n] = W1[(size_t)(n0 + n) * HH + k0 + k];
            }
            __syncthreads();
            #pragma unroll
            for (int kk = 0; kk < 16; kk++) {
                float a[4];
                #pragma unroll
                for (int i = 0; i < 4; i++)
                    a[i] = As[(ty * 4 + i) * APAD + k0 + kk];
                float4 b4 = *(const float4*)&Bs[kk * 68 + tx * 4];
                #pragma unroll
                for (int i = 0; i < 4; i++) {
                    acc[i][0] += a[i] * b4.x;
                    acc[i][1] += a[i] * b4.y;
                    acc[i][2] += a[i] * b4.z;
                    acc[i][3] += a[i] * b4.w;
                }
            }
            __syncthreads();
        }
        // epilogue: tanh + Vw-weighted row partial
        #pragma unroll
        for (int j = 0; j < 4; j++) {
            int n = n0 + tx * 4 + j;
            float uv = urow[n] + W1b[n];
            float vw = Vw[n];
            #pragma unroll
            for (int i = 0; i < 4; i++)
                rpart[i] += tanhf(acc[i][j] + uv) * vw;
        }
    }
    // reduce across the 16 tx lanes (contiguous half-warp segments)
    float vb = Vb[0];
    #pragma unroll
    for (int i = 0; i < 4; i++) {
        float v = rpart[i];
        #pragma unroll
        for (int off = 8; off > 0; off >>= 1)
            v += __shfl_down_sync(0xffffffffu, v, off, 16);
        if (tx == 0) logits[m0 + ty * 4 + i] = v + vb;
    }
}

// ---------------- softmax over S + context vector ----------------
__global__ void __launch_bounds__(256) softmax_ctx(
    const float* __restrict__ logits, const float* __restrict__ enc,
    float* __restrict__ gin)
{
    __shared__ float w[SS];
    __shared__ float red[256];
    const int b = blockIdx.x, tid = threadIdx.x;
    float v = (tid < SS) ? logits[b * SS + tid] : -1e30f;
    red[tid] = v; __syncthreads();
    for (int s = 128; s > 0; s >>= 1) {
        if (tid < s) red[tid] = fmaxf(red[tid], red[tid + s]);
        __syncthreads();
    }
    float mx = red[0]; __syncthreads();
    float e = (tid < SS) ? expf(v - mx) : 0.f;
    red[tid] = e; __syncthreads();
    for (int s = 128; s > 0; s >>= 1) {
        if (tid < s) red[tid] += red[tid + s];
        __syncthreads();
    }
    float inv = 1.f / red[0];
    if (tid < SS) w[tid] = e * inv;
    __syncthreads();

    const float* encb = enc + (size_t)b * SS * HH;
    for (int h = tid; h < HH; h += 256) {
        float acc = 0.f;
        #pragma unroll 4
        for (int s = 0; s < SS; s++)
            acc += w[s] * encb[s * HH + h];
        gin[(size_t)b * GIN_W + h] = acc;
    }
}

// ---------------- embedding gather into gin[:, H:H+E] ----------------
__global__ void emb_gather(const int* __restrict__ x,
                           const float* __restrict__ emb_table,
                           float* __restrict__ gin)
{
    int i = blockIdx.x * blockDim.x + threadIdx.x;
    if (i >= BB * EE) return;
    int b = i / EE, e = i - b * EE;
    int tok = x[b];
    gin[(size_t)b * GIN_W + HH + e] = emb_table[(size_t)tok * EE + e];
}

// ---------------- GRU pointwise ----------------
__global__ void gru_pointwise(const float* __restrict__ gi,
                              const float* __restrict__ gh,
                              const float* __restrict__ h0,
                              float* __restrict__ hnew,
                              float* __restrict__ hout)
{
    int i = blockIdx.x * blockDim.x + threadIdx.x;
    if (i >= BB * HH) return;
    int b = i / HH, h = i - b * HH;
    size_t base = (size_t)b * H3 + h;
    float i_r = gi[base], i_z = gi[base + HH], i_n = gi[base + 2 * HH];
    float h_r = gh[base], h_z = gh[base + HH], h_n = gh[base + 2 * HH];
    float r = 1.f / (1.f + expf(-(i_r + h_r)));
    float z = 1.f / (1.f + expf(-(i_z + h_z)));
    float n = tanhf(i_n + r * h_n);
    float h0v = h0[i];
    float hn = (1.f - z) * n + z * h0v;
    hnew[i] = hn;
    hout[i] = hn;
}

// ---------------- launch ----------------
extern "C" void kernel_launch(void* const* d_in, const int* in_sizes, int n_in,
                              void* d_out, int out_size)
{
    const int*   x        = (const int*)  d_in[0];
    const float* hidden   = (const float*)d_in[1];   // [1,B,H] -> h0 = [B,H]
    const float* enc      = (const float*)d_in[2];   // [B,S,H]
    const float* emb_t    = (const float*)d_in[3];   // [V,E]
    const float* W1_w     = (const float*)d_in[4];
    const float* W1_b     = (const float*)d_in[5];
    const float* W2_w     = (const float*)d_in[6];
    const float* W2_b     = (const float*)d_in[7];
    const float* V_w      = (const float*)d_in[8];
    const float* V_b      = (const float*)d_in[9];
    const float* gru_w_ih = (const float*)d_in[10];
    const float* gru_w_hh = (const float*)d_in[11];
    const float* gru_b_ih = (const float*)d_in[12];
    const float* gru_b_hh = (const float*)d_in[13];
    const float* fc1_w    = (const float*)d_in[14];
    const float* fc1_b    = (const float*)d_in[15];
    const float* fc2_w    = (const float*)d_in[16];
    const float* fc2_b    = (const float*)d_in[17];

    float* y_out = (float*)d_out;                 // [B,V]
    float* h_out = y_out + (size_t)BB * VV;       // [1,B,H]

    float *p_u, *p_gh, *p_logits, *p_gin, *p_gi, *p_hnew, *p_a1;
    cudaGetSymbolAddress((void**)&p_u,      g_u);
    cudaGetSymbolAddress((void**)&p_gh,     g_gh);
    cudaGetSymbolAddress((void**)&p_logits, g_logits);
    cudaGetSymbolAddress((void**)&p_gin,    g_gin);
    cudaGetSymbolAddress((void**)&p_gi,     g_gi);
    cudaGetSymbolAddress((void**)&p_hnew,   g_hnew);
    cudaGetSymbolAddress((void**)&p_a1,     g_a1);

    const int attn_smem = (64 * APAD + 16 * 68) * (int)sizeof(float);
    cudaFuncSetAttribute(attn_logits, cudaFuncAttributeMaxDynamicSharedMemorySize, attn_smem);

    // u = h0 @ W2^T + W2_b     [B,H]
    sgemm_bt<0><<<dim3(HH / 64, BB / 64), 256>>>(hidden, W2_w, W2_b, p_u, BB, HH, HH);
    // gh = h0 @ gru_w_hh^T + gru_b_hh    [B,3H]
    sgemm_bt<0><<<dim3(H3 / 64, BB / 64), 256>>>(hidden, gru_w_hh, gru_b_hh, p_gh, BB, H3, HH);
    // attention logits (fused big GEMM + tanh + Vw dot)
    attn_logits<<<MROWS / 64, 256, attn_smem>>>(enc, W1_w, W1_b, p_u, V_w, V_b, p_logits);
    // softmax + ctx -> gin[:, :H]
    softmax_ctx<<<BB, 256>>>(p_logits, enc, p_gin);
    // emb gather -> gin[:, H:]
    emb_gather<<<(BB * EE + 255) / 256, 256>>>(x, emb_t, p_gin);
    // gi = gin @ gru_w_ih^T + gru_b_ih   [B,3H], K=812
    sgemm_bt<0><<<dim3(H3 / 64, BB / 64), 256>>>(p_gin, gru_w_ih, gru_b_ih, p_gi, BB, H3, GIN_W);
    // GRU pointwise -> hnew (scratch + output)
    gru_pointwise<<<(BB * HH + 255) / 256, 256>>>(p_gi, p_gh, hidden, p_hnew, h_out);
    // a1 = leaky_relu(hnew @ fc1_w^T + fc1_b)   [B,E]
    sgemm_bt<1><<<dim3((EE + 63) / 64, BB / 64), 256>>>(p_hnew, fc1_w, fc1_b, p_a1, BB, EE, HH);
    // y = a1 @ fc2_w^T + fc2_b   [B,V]
    sgemm_bt<0><<<dim3(VV / 64, BB / 64), 256>>>(p_a1, fc2_w, fc2_b, y_out, BB, VV, EE);
}

// round 4
// speedup vs baseline: 2.8078x; 2.8078x over previous
#include <cuda_runtime.h>
#include <cuda_bf16.h>
#include <math.h>
#include <stdint.h>

// Problem dims
#define BB 2048
#define SS 128
#define VV 128
#define EE 300
#define HH 512
#define GIN_W (HH + EE)      // 812
#define H3 (3 * HH)          // 1536

// ---------------- scratch (device globals; no allocation allowed) ----------------
__device__ float g_u[BB * HH];
__device__ float g_gh[BB * H3];
__device__ float g_logits[BB * SS];
__device__ float g_gin[BB * GIN_W];
__device__ float g_gi[BB * H3];
__device__ float g_hnew[BB * HH];
__device__ float g_a1[BB * EE];
__device__ __nv_bfloat16 g_w1hi[HH * HH];
__device__ __nv_bfloat16 g_w1lo[HH * HH];

// ================= helpers =================
__device__ __forceinline__ uint32_t smem_u32(const void* p) {
    uint32_t a;
    asm("{ .reg .u64 t; cvta.to.shared.u64 t, %1; cvt.u32.u64 %0, t; }" : "=r"(a) : "l"(p));
    return a;
}
__device__ __forceinline__ void ldm_x4(uint32_t* r, uint32_t addr) {
    asm volatile("ldmatrix.sync.aligned.m8n8.x4.shared.b16 {%0,%1,%2,%3}, [%4];"
        : "=r"(r[0]), "=r"(r[1]), "=r"(r[2]), "=r"(r[3]) : "r"(addr));
}
__device__ __forceinline__ void mma16816(float* c, const uint32_t* a, const uint32_t* b) {
    asm volatile("mma.sync.aligned.m16n8k16.row.col.f32.bf16.bf16.f32 "
        "{%0,%1,%2,%3}, {%4,%5,%6,%7}, {%8,%9}, {%0,%1,%2,%3};"
        : "+f"(c[0]), "+f"(c[1]), "+f"(c[2]), "+f"(c[3])
        : "r"(a[0]), "r"(a[1]), "r"(a[2]), "r"(a[3]), "r"(b[0]), "r"(b[1]));
}
__device__ __forceinline__ void cpasync16(uint32_t dst, const void* src) {
    asm volatile("cp.async.cg.shared.global [%0], [%1], 16;" :: "r"(dst), "l"(src) : "memory");
}
#define CP_COMMIT() asm volatile("cp.async.commit_group;" ::: "memory")

__device__ __forceinline__ uint32_t pack_bf2(float a, float b) {
    __nv_bfloat162 t = __floats2bfloat162_rn(a, b);
    return *(uint32_t*)&t;
}
__device__ __forceinline__ float tanh_acc(float x) {
    x = fminf(fmaxf(x, -15.f), 15.f);
    float e = __expf(2.f * x);
    return __fdividef(e - 1.f, e + 1.f);
}

// ================= W1 split prep =================
__global__ void w1_split(const float* __restrict__ w,
                         __nv_bfloat16* __restrict__ hi,
                         __nv_bfloat16* __restrict__ lo) {
    int i = blockIdx.x * 256 + threadIdx.x;
    if (i < HH * HH) {
        float v = w[i];
        __nv_bfloat16 h = __float2bfloat16(v);
        hi[i] = h;
        lo[i] = __float2bfloat16(v - __bfloat162float(h));
    }
}

// ================= fused attention logits via mma.sync (HMMA bf16, split 3-pass) =================
// Per CTA: 64 seq rows of one batch b. A slab (64x512, hi+lo bf16, swizzled) resident in smem.
// N=512 swept as 4 tiles of 128; K streamed in 64-wide chunks (B hi+lo, cp.async double buffer).
// Epilogue folds tanh + V_w dot; logits written directly.
//
// smem layout (bytes):
#define SA_HI   0         // 64 rows x 1024 B   (64x512 bf16, swizzled)
#define SA_LO   65536
#define SB_OFF  131072    // 2 bufs x (hi 16384 + lo 16384)
#define UVW_OFF 196608    // float2[512]
#define PART_OFF 200704   // float[128]
#define ATT_SMEM 201728

__global__ void __launch_bounds__(256) attn_mma(
    const float* __restrict__ enc,
    const __nv_bfloat16* __restrict__ w1hi, const __nv_bfloat16* __restrict__ w1lo,
    const float* __restrict__ W1b, const float* __restrict__ u,
    const float* __restrict__ Vw, const float* __restrict__ Vb,
    float* __restrict__ logits)
{
    extern __shared__ __align__(128) char sm[];
    const uint32_t smb = smem_u32(sm);
    const int tid = threadIdx.x, wid = tid >> 5, lane = tid & 31;
    const int m0 = blockIdx.x * 64;
    const int b = blockIdx.x >> 1;

    // uvw[n] = (u[b][n] + W1b[n], Vw[n])
    float2* uvw = (float2*)(sm + UVW_OFF);
    for (int n = tid; n < HH; n += 256)
        uvw[n] = make_float2(u[(size_t)b * HH + n] + W1b[n], Vw[n]);

    // ---- A slab: load enc fp32, split to bf16 hi/lo, store swizzled ----
    // chunk = 16B = 8 bf16; row r: chunk c stored at c ^ (r&7) (low 3 bits)
    #pragma unroll
    for (int it = 0; it < 16; it++) {
        int idx = tid + it * 256;          // 0..4095 chunks
        int r = idx >> 6, c = idx & 63;
        const float4* src = (const float4*)(enc + (size_t)(m0 + r) * HH + c * 8);
        float4 v0 = src[0], v1 = src[1];
        float f[8] = {v0.x, v0.y, v0.z, v0.w, v1.x, v1.y, v1.z, v1.w};
        float h[8], l[8];
        #pragma unroll
        for (int j = 0; j < 8; j++) {
            h[j] = __bfloat162float(__float2bfloat16(f[j]));
            l[j] = f[j] - h[j];
        }
        uint4 hv, lv;
        hv.x = pack_bf2(h[0], h[1]); hv.y = pack_bf2(h[2], h[3]);
        hv.z = pack_bf2(h[4], h[5]); hv.w = pack_bf2(h[6], h[7]);
        lv.x = pack_bf2(l[0], l[1]); lv.y = pack_bf2(l[2], l[3]);
        lv.z = pack_bf2(l[4], l[5]); lv.w = pack_bf2(l[6], l[7]);
        uint32_t off = (uint32_t)(r * 1024 + ((c ^ (r & 7)) << 4));
        *(uint4*)(sm + SA_HI + off) = hv;
        *(uint4*)(sm + SA_LO + off) = lv;
    }
    __syncthreads();

    // ---- warp tiling constants ----
    const int mb = wid & 3;            // 16-row m block
    const int nw2 = wid >> 2;          // 64-col n block
    const int arow = mb * 16 + (lane & 15);
    const uint32_t aBase = smb + SA_HI + arow * 1024;
    const int aswz = arow & 7;
    int bswz[4]; uint32_t bBase[4];
    #pragma unroll
    for (int f16 = 0; f16 < 4; f16++) {
        int rb = nw2 * 64 + f16 * 16 + (lane & 15);   // local n-row in B tile
        bBase[f16] = smb + SB_OFF + rb * 128;
        bswz[f16] = rb & 7;
    }
    const int klane = (lane >> 4) << 3;   // 0 or 8

    float acc[8][4] = {};
    float rp0 = 0.f, rp1 = 0.f;

    // ---- B prefetch (chunk = nt,kc -> 128n x 64k hi+lo = 32 KB) ----
    auto prefetch = [&](int itc) {
        int nt = itc >> 3, kc = itc & 7, buf = itc & 1;
        #pragma unroll
        for (int it2 = 0; it2 < 4; it2++) {
            int idx = tid + it2 * 256;           // 0..1023
            int r = idx >> 3, c = idx & 7;
            uint32_t dst = smb + SB_OFF + buf * 32768 + r * 128 + ((uint32_t)(c ^ (r & 7)) << 4);
            size_t gofs = (size_t)(nt * 128 + r) * HH + kc * 64 + c * 8;
            cpasync16(dst,         w1hi + gofs);
            cpasync16(dst + 16384, w1lo + gofs);
        }
        CP_COMMIT();
    };

    prefetch(0);

    for (int itc = 0; itc < 32; itc++) {
        const int nt = itc >> 3, kc = itc & 7, buf = itc & 1;
        if (itc < 31) {
            prefetch(itc + 1);
            asm volatile("cp.async.wait_group 1;" ::: "memory");
        } else {
            asm volatile("cp.async.wait_group 0;" ::: "memory");
        }
        __syncthreads();

        #pragma unroll
        for (int ks = 0; ks < 4; ks++) {
            uint32_t ah[4], al[4];
            int achunk = kc * 8 + ks * 2 + (lane >> 4);
            uint32_t aaddr = aBase + ((uint32_t)(achunk ^ aswz) << 4);
            ldm_x4(ah, aaddr);
            ldm_x4(al, aaddr + 65536);

            uint32_t bh[4][4], bl[4][4];
            int bchunk = ks * 2 + (lane >> 4);
            #pragma unroll
            for (int f16 = 0; f16 < 4; f16++) {
                uint32_t baddr = bBase[f16] + buf * 32768 + ((uint32_t)(bchunk ^ bswz[f16]) << 4);
                ldm_x4(bh[f16], baddr);
                ldm_x4(bl[f16], baddr + 16384);
            }
            #pragma unroll
            for (int f16 = 0; f16 < 4; f16++) {
                uint32_t bfh0[2] = {bh[f16][0], bh[f16][2]};
                uint32_t bfh1[2] = {bh[f16][1], bh[f16][3]};
                uint32_t bfl0[2] = {bl[f16][0], bl[f16][2]};
                uint32_t bfl1[2] = {bl[f16][1], bl[f16][3]};
                mma16816(acc[f16 * 2],     ah, bfh0);
                mma16816(acc[f16 * 2],     ah, bfl0);
                mma16816(acc[f16 * 2],     al, bfh0);
                mma16816(acc[f16 * 2 + 1], ah, bfh1);
                mma16816(acc[f16 * 2 + 1], ah, bfl1);
                mma16816(acc[f16 * 2 + 1], al, bfh1);
            }
        }
        __syncthreads();   // protect buffer reuse by next prefetch

        if (kc == 7) {
            // epilogue for this 128-col N tile: tanh + Vw dot into row partials
            #pragma unroll
            for (int f = 0; f < 8; f++) {
                int n = nt * 128 + nw2 * 64 + f * 8 + ((lane & 3) << 1);
                float2 u0 = uvw[n], u1 = uvw[n + 1];
                rp0 += tanh_acc(acc[f][0] + u0.x) * u0.y;
                rp0 += tanh_acc(acc[f][1] + u1.x) * u1.y;
                rp1 += tanh_acc(acc[f][2] + u0.x) * u0.y;
                rp1 += tanh_acc(acc[f][3] + u1.x) * u1.y;
                acc[f][0] = acc[f][1] = acc[f][2] = acc[f][3] = 0.f;
            }
        }
    }

    // reduce 4 lanes sharing a row (lanes 4g..4g+3)
    rp0 += __shfl_down_sync(0xffffffffu, rp0, 2, 4);
    rp0 += __shfl_down_sync(0xffffffffu, rp0, 1, 4);
    rp1 += __shfl_down_sync(0xffffffffu, rp1, 2, 4);
    rp1 += __shfl_down_sync(0xffffffffu, rp1, 1, 4);
    float* part = (float*)(sm + PART_OFF);
    if ((lane & 3) == 0) {
        int rl = mb * 16 + (lane >> 2);
        part[nw2 * 64 + rl]     = rp0;
        part[nw2 * 64 + rl + 8] = rp1;
    }
    __syncthreads();
    if (tid < 64)
        logits[m0 + tid] = part[tid] + part[64 + tid] + Vb[0];
}

// ---------------- generic tiled SGEMM: C[M,N] = A[M,K] @ B[N,K]^T + bias ----------------
template<int ACT>
__global__ void __launch_bounds__(256) sgemm_bt(
    const float* __restrict__ A, const float* __restrict__ Bm,
    const float* __restrict__ bias, float* __restrict__ C,
    int M, int N, int K)
{
    __shared__ float As[16][65];
    __shared__ float Bs[16][65];
    const int tid = threadIdx.x;
    const int tx = tid & 15, ty = tid >> 4;
    const int m0 = blockIdx.y * 64, n0 = blockIdx.x * 64;

    float acc[4][4] = {};
    for (int k0 = 0; k0 < K; k0 += 16) {
        #pragma unroll
        for (int r = 0; r < 4; r++) {
            int i = tid + r * 256;
            int m = i >> 4, k = i & 15;
            float v = 0.f;
            if (m0 + m < M && k0 + k < K) v = A[(size_t)(m0 + m) * K + k0 + k];
            As[k][m] = v;
        }
        #pragma unroll
        for (int r = 0; r < 4; r++) {
            int i = tid + r * 256;
            int n = i >> 4, k = i & 15;
            float v = 0.f;
            if (n0 + n < N && k0 + k < K) v = Bm[(size_t)(n0 + n) * K + k0 + k];
            Bs[k][n] = v;
        }
        __syncthreads();
        #pragma unroll
        for (int kk = 0; kk < 16; kk++) {
            float a[4], bv[4];
            #pragma unroll
            for (int i = 0; i < 4; i++) a[i] = As[kk][ty * 4 + i];
            #pragma unroll
            for (int j = 0; j < 4; j++) bv[j] = Bs[kk][tx * 4 + j];
            #pragma unroll
            for (int i = 0; i < 4; i++)
                #pragma unroll
                for (int j = 0; j < 4; j++)
                    acc[i][j] += a[i] * bv[j];
        }
        __syncthreads();
    }
    #pragma unroll
    for (int i = 0; i < 4; i++) {
        int m = m0 + ty * 4 + i;
        if (m >= M) break;
        #pragma unroll
        for (int j = 0; j < 4; j++) {
            int n = n0 + tx * 4 + j;
            if (n < N) {
                float v = acc[i][j] + (bias ? bias[n] : 0.f);
                if (ACT == 1) v = (v > 0.f) ? v : 0.01f * v;
                C[(size_t)m * N + n] = v;
            }
        }
    }
}

// ---------------- softmax over S + context vector ----------------
__global__ void __launch_bounds__(256) softmax_ctx(
    const float* __restrict__ logits, const float* __restrict__ enc,
    float* __restrict__ gin)
{
    __shared__ float w[SS];
    __shared__ float red[256];
    const int b = blockIdx.x, tid = threadIdx.x;
    float v = (tid < SS) ? logits[b * SS + tid] : -1e30f;
    red[tid] = v; __syncthreads();
    for (int s = 128; s > 0; s >>= 1) {
        if (tid < s) red[tid] = fmaxf(red[tid], red[tid + s]);
        __syncthreads();
    }
    float mx = red[0]; __syncthreads();
    float e = (tid < SS) ? expf(v - mx) : 0.f;
    red[tid] = e; __syncthreads();
    for (int s = 128; s > 0; s >>= 1) {
        if (tid < s) red[tid] += red[tid + s];
        __syncthreads();
    }
    float inv = 1.f / red[0];
    if (tid < SS) w[tid] = e * inv;
    __syncthreads();

    const float* encb = enc + (size_t)b * SS * HH;
    for (int h = tid; h < HH; h += 256) {
        float acc = 0.f;
        #pragma unroll 4
        for (int s = 0; s < SS; s++)
            acc += w[s] * encb[s * HH + h];
        gin[(size_t)b * GIN_W + h] = acc;
    }
}

// ---------------- embedding gather into gin[:, H:H+E] ----------------
__global__ void emb_gather(const int* __restrict__ x,
                           const float* __restrict__ emb_table,
                           float* __restrict__ gin)
{
    int i = blockIdx.x * blockDim.x + threadIdx.x;
    if (i >= BB * EE) return;
    int b = i / EE, e = i - b * EE;
    int tok = x[b];
    gin[(size_t)b * GIN_W + HH + e] = emb_table[(size_t)tok * EE + e];
}

// ---------------- GRU pointwise ----------------
__global__ void gru_pointwise(const float* __restrict__ gi,
                              const float* __restrict__ gh,
                              const float* __restrict__ h0,
                              float* __restrict__ hnew,
                              float* __restrict__ hout)
{
    int i = blockIdx.x * blockDim.x + threadIdx.x;
    if (i >= BB * HH) return;
    int b = i / HH, h = i - b * HH;
    size_t base = (size_t)b * H3 + h;
    float i_r = gi[base], i_z = gi[base + HH], i_n = gi[base + 2 * HH];
    float h_r = gh[base], h_z = gh[base + HH], h_n = gh[base + 2 * HH];
    float r = 1.f / (1.f + expf(-(i_r + h_r)));
    float z = 1.f / (1.f + expf(-(i_z + h_z)));
    float n = tanhf(i_n + r * h_n);
    float h0v = h0[i];
    float hn = (1.f - z) * n + z * h0v;
    hnew[i] = hn;
    hout[i] = hn;
}

// ---------------- launch ----------------
extern "C" void kernel_launch(void* const* d_in, const int* in_sizes, int n_in,
                              void* d_out, int out_size)
{
    const int*   x        = (const int*)  d_in[0];
    const float* hidden   = (const float*)d_in[1];
    const float* enc      = (const float*)d_in[2];
    const float* emb_t    = (const float*)d_in[3];
    const float* W1_w     = (const float*)d_in[4];
    const float* W1_b     = (const float*)d_in[5];
    const float* W2_w     = (const float*)d_in[6];
    const float* W2_b     = (const float*)d_in[7];
    const float* V_w      = (const float*)d_in[8];
    const float* V_b      = (const float*)d_in[9];
    const float* gru_w_ih = (const float*)d_in[10];
    const float* gru_w_hh = (const float*)d_in[11];
    const float* gru_b_ih = (const float*)d_in[12];
    const float* gru_b_hh = (const float*)d_in[13];
    const float* fc1_w    = (const float*)d_in[14];
    const float* fc1_b    = (const float*)d_in[15];
    const float* fc2_w    = (const float*)d_in[16];
    const float* fc2_b    = (const float*)d_in[17];

    float* y_out = (float*)d_out;
    float* h_out = y_out + (size_t)BB * VV;

    float *p_u, *p_gh, *p_logits, *p_gin, *p_gi, *p_hnew, *p_a1;
    __nv_bfloat16 *p_w1hi, *p_w1lo;
    cudaGetSymbolAddress((void**)&p_u,      g_u);
    cudaGetSymbolAddress((void**)&p_gh,     g_gh);
    cudaGetSymbolAddress((void**)&p_logits, g_logits);
    cudaGetSymbolAddress((void**)&p_gin,    g_gin);
    cudaGetSymbolAddress((void**)&p_gi,     g_gi);
    cudaGetSymbolAddress((void**)&p_hnew,   g_hnew);
    cudaGetSymbolAddress((void**)&p_a1,     g_a1);
    cudaGetSymbolAddress((void**)&p_w1hi,   g_w1hi);
    cudaGetSymbolAddress((void**)&p_w1lo,   g_w1lo);

    cudaFuncSetAttribute(attn_mma, cudaFuncAttributeMaxDynamicSharedMemorySize, ATT_SMEM);

    // W1 -> bf16 hi/lo
    w1_split<<<(HH * HH + 255) / 256, 256>>>(W1_w, p_w1hi, p_w1lo);
    // u = h0 @ W2^T + W2_b
    sgemm_bt<0><<<dim3(HH / 64, BB / 64), 256>>>(hidden, W2_w, W2_b, p_u, BB, HH, HH);
    // gh = h0 @ gru_w_hh^T + gru_b_hh
    sgemm_bt<0><<<dim3(H3 / 64, BB / 64), 256>>>(hidden, gru_w_hh, gru_b_hh, p_gh, BB, H3, HH);
    // attention logits: HMMA split-bf16 GEMM + tanh + Vw dot (score never materialized)
    attn_mma<<<BB * 2, 256, ATT_SMEM>>>(enc, p_w1hi, p_w1lo, W1_b, p_u, V_w, V_b, p_logits);
    // softmax + ctx -> gin[:, :H]
    softmax_ctx<<<BB, 256>>>(p_logits, enc, p_gin);
    // emb gather -> gin[:, H:]
    emb_gather<<<(BB * EE + 255) / 256, 256>>>(x, emb_t, p_gin);
    // gi = gin @ gru_w_ih^T + gru_b_ih
    sgemm_bt<0><<<dim3(H3 / 64, BB / 64), 256>>>(p_gin, gru_w_ih, gru_b_ih, p_gi, BB, H3, GIN_W);
    // GRU pointwise
    gru_pointwise<<<(BB * HH + 255) / 256, 256>>>(p_gi, p_gh, hidden, p_hnew, h_out);
    // a1 = leaky_relu(hnew @ fc1_w^T + fc1_b)
    sgemm_bt<1><<<dim3((EE + 63) / 64, BB / 64), 256>>>(p_hnew, fc1_w, fc1_b, p_a1, BB, EE, HH);
    // y = a1 @ fc2_w^T + fc2_b
    sgemm_bt<0><<<dim3(VV / 64, BB / 64), 256>>>(p_a1, fc2_w, fc2_b, y_out, BB, VV, EE);
}

// round 7
// speedup vs baseline: 3.7977x; 1.3526x over previous
#include <cuda_runtime.h>
#include <cuda_bf16.h>
#include <math.h>
#include <stdint.h>

// Problem dims
#define BB 2048
#define SS 128
#define VV 128
#define EE 300
#define HH 512
#define H3 (3 * HH)          // 1536
#define KIH 832              // padded 812
#define KF  384              // fc1 output / fc2 K padding (300 -> 384)

// ---------------- scratch (device globals) ----------------
__device__ float g_ug[BB * 2048];            // [u | gh]
__device__ float g_gi[BB * H3];
__device__ float g_logits[BB * SS];
__device__ __nv_bfloat16 g_hid_hi[BB * HH],  g_hid_lo[BB * HH];
__device__ __nv_bfloat16 g_wc_hi[2048 * HH], g_wc_lo[2048 * HH];     // [W2; gru_w_hh]
__device__ __nv_bfloat16 g_w1hi[HH * HH],    g_w1lo[HH * HH];
__device__ __nv_bfloat16 g_wih_hi[H3 * KIH], g_wih_lo[H3 * KIH];
__device__ __nv_bfloat16 g_gin_hi[BB * KIH], g_gin_lo[BB * KIH];
__device__ __nv_bfloat16 g_hn_hi[BB * HH],   g_hn_lo[BB * HH];
__device__ __nv_bfloat16 g_fc1_hi[KF * HH],  g_fc1_lo[KF * HH];
__device__ __nv_bfloat16 g_fc2_hi[VV * KF],  g_fc2_lo[VV * KF];
__device__ __nv_bfloat16 g_a1_hi[BB * KF],   g_a1_lo[BB * KF];
__device__ float g_bc[2048];
__device__ float g_bfc1[KF];

// ================= helpers =================
__device__ __forceinline__ uint32_t smem_u32(const void* p) {
    uint32_t a;
    asm("{ .reg .u64 t; cvta.to.shared.u64 t, %1; cvt.u32.u64 %0, t; }" : "=r"(a) : "l"(p));
    return a;
}
__device__ __forceinline__ void ldm_x4(uint32_t* r, uint32_t addr) {
    asm volatile("ldmatrix.sync.aligned.m8n8.x4.shared.b16 {%0,%1,%2,%3}, [%4];"
        : "=r"(r[0]), "=r"(r[1]), "=r"(r[2]), "=r"(r[3]) : "r"(addr));
}
__device__ __forceinline__ void mma16816(float* c, const uint32_t* a, const uint32_t* b) {
    asm volatile("mma.sync.aligned.m16n8k16.row.col.f32.bf16.bf16.f32 "
        "{%0,%1,%2,%3}, {%4,%5,%6,%7}, {%8,%9}, {%0,%1,%2,%3};"
        : "+f"(c[0]), "+f"(c[1]), "+f"(c[2]), "+f"(c[3])
        : "r"(a[0]), "r"(a[1]), "r"(a[2]), "r"(a[3]), "r"(b[0]), "r"(b[1]));
}
__device__ __forceinline__ void cpasync16(uint32_t dst, const void* src) {
    asm volatile("cp.async.cg.shared.global [%0], [%1], 16;" :: "r"(dst), "l"(src) : "memory");
}
#define CP_COMMIT() asm volatile("cp.async.commit_group;" ::: "memory")

__device__ __forceinline__ uint32_t pack_bf2(float a, float b) {
    __nv_bfloat162 t = __floats2bfloat162_rn(a, b);
    return *(uint32_t*)&t;
}
__device__ __forceinline__ float tanh_acc(float x) {
    x = fminf(fmaxf(x, -15.f), 15.f);
    float e = __expf(2.f * x);
    return __fdividef(e - 1.f, e + 1.f);
}
__device__ __forceinline__ void split2(float v, __nv_bfloat16& h, __nv_bfloat16& l) {
    h = __float2bfloat16(v);
    l = __float2bfloat16(v - __bfloat162float(h));
}

// ================= prep: split/pad =================
__global__ void split_pad(const float* __restrict__ src, int R, int C,
                          __nv_bfloat16* __restrict__ hi, __nv_bfloat16* __restrict__ lo,
                          int Rp, int Cp, int rowOff)
{
    int i = blockIdx.x * 256 + threadIdx.x;
    if (i >= Rp * Cp) return;
    int r = i / Cp, c = i - r * Cp;
    float v = (r < R && c < C) ? src[(size_t)r * C + c] : 0.f;
    __nv_bfloat16 h, l; split2(v, h, l);
    size_t o = (size_t)(r + rowOff) * Cp + c;
    hi[o] = h; lo[o] = l;
}
__global__ void pad_bias(const float* __restrict__ src, int n,
                         float* __restrict__ dst, int np, int off)
{
    int i = blockIdx.x * 256 + threadIdx.x;
    if (i < np) dst[off + i] = (i < n) ? src[i] : 0.f;
}

// ================= generic HMMA split-bf16 GEMM =================
// C[M,N] = A[M,K] @ B[N,K]^T + bias ; 3-pass split (A,B pre-split hi/lo bf16)
// CTA: 64M x 128N; 256 threads; 8 warps in 2M x 4N (warp tile 32x32)
// OUT=0: fp32 C  ;  OUT=1: leaky_relu then split-bf16 (Chi, Clo)
#define HG_SMEM 98304
template<int OUT>
__global__ void __launch_bounds__(256) hgemm_bt_mma(
    const __nv_bfloat16* __restrict__ Ahi, const __nv_bfloat16* __restrict__ Alo,
    const __nv_bfloat16* __restrict__ Bhi, const __nv_bfloat16* __restrict__ Blo,
    const float* __restrict__ bias, float* __restrict__ C,
    __nv_bfloat16* __restrict__ Chi, __nv_bfloat16* __restrict__ Clo,
    int K, int lda, int ldc)
{
    extern __shared__ __align__(128) char sm[];
    const uint32_t smb = smem_u32(sm);
    const int tid = threadIdx.x, wid = tid >> 5, lane = tid & 31;
    const int mb = wid & 1, nw = wid >> 1;
    const int m0 = blockIdx.y * 64, n0 = blockIdx.x * 128;
    const int nk = K >> 6;

    auto prefetch = [&](int kc) {
        uint32_t base = smb + (uint32_t)(kc & 1) * 49152;
        #pragma unroll
        for (int it = 0; it < 2; it++) {
            int idx = tid + it * 256;
            int r = idx >> 3, c = idx & 7;
            uint32_t dst = base + r * 128 + ((uint32_t)(c ^ (r & 7)) << 4);
            size_t go = (size_t)(m0 + r) * lda + kc * 64 + c * 8;
            cpasync16(dst,        Ahi + go);
            cpasync16(dst + 8192, Alo + go);
        }
        #pragma unroll
        for (int it = 0; it < 4; it++) {
            int idx = tid + it * 256;
            int r = idx >> 3, c = idx & 7;
            uint32_t dst = base + 16384 + r * 128 + ((uint32_t)(c ^ (r & 7)) << 4);
            size_t go = (size_t)(n0 + r) * K + kc * 64 + c * 8;
            cpasync16(dst,         Bhi + go);
            cpasync16(dst + 16384, Blo + go);
        }
        CP_COMMIT();
    };

    float acc[2][4][4] = {};
    const int aswz = lane & 7;
    prefetch(0);

    for (int kc = 0; kc < nk; kc++) {
        if (kc + 1 < nk) {
            prefetch(kc + 1);
            asm volatile("cp.async.wait_group 1;" ::: "memory");
        } else {
            asm volatile("cp.async.wait_group 0;" ::: "memory");
        }
        __syncthreads();
        uint32_t base = smb + (uint32_t)(kc & 1) * 49152;
        uint32_t aB[2], bB[2];
        #pragma unroll
        for (int f = 0; f < 2; f++) {
            aB[f] = base + (mb * 32 + f * 16 + (lane & 15)) * 128;
            bB[f] = base + 16384 + (nw * 32 + f * 16 + (lane & 15)) * 128;
        }
        #pragma unroll
        for (int ks = 0; ks < 4; ks++) {
            int chunk = ks * 2 + (lane >> 4);
            uint32_t coff = (uint32_t)(chunk ^ aswz) << 4;
            uint32_t ah[2][4], al[2][4], bh[2][4], bl[2][4];
            #pragma unroll
            for (int f = 0; f < 2; f++) {
                ldm_x4(ah[f], aB[f] + coff);
                ldm_x4(al[f], aB[f] + coff + 8192);
                ldm_x4(bh[f], bB[f] + coff);
                ldm_x4(bl[f], bB[f] + coff + 16384);
            }
            #pragma unroll
            for (int m = 0; m < 2; m++)
                #pragma unroll
                for (int f2 = 0; f2 < 2; f2++)
                    #pragma unroll
                    for (int sel = 0; sel < 2; sel++) {
                        int n8 = f2 * 2 + sel;
                        uint32_t bfh[2] = { bh[f2][sel], bh[f2][sel + 2] };
                        uint32_t bfl[2] = { bl[f2][sel], bl[f2][sel + 2] };
                        mma16816(acc[m][n8], ah[m], bfh);
                        mma16816(acc[m][n8], ah[m], bfl);
                        mma16816(acc[m][n8], al[m], bfh);
                    }
        }
        __syncthreads();
    }

    // epilogue
    #pragma unroll
    for (int f = 0; f < 2; f++) {
        int r0 = m0 + mb * 32 + f * 16 + (lane >> 2);
        int r1 = r0 + 8;
        #pragma unroll
        for (int n8 = 0; n8 < 4; n8++) {
            int col = n0 + nw * 32 + n8 * 8 + ((lane & 3) << 1);
            float b0 = bias[col], b1 = bias[col + 1];
            float v00 = acc[f][n8][0] + b0, v01 = acc[f][n8][1] + b1;
            float v10 = acc[f][n8][2] + b0, v11 = acc[f][n8][3] + b1;
            if (OUT == 0) {
                *(float2*)&C[(size_t)r0 * ldc + col] = make_float2(v00, v01);
                *(float2*)&C[(size_t)r1 * ldc + col] = make_float2(v10, v11);
            } else {
                v00 = (v00 > 0.f) ? v00 : 0.01f * v00;
                v01 = (v01 > 0.f) ? v01 : 0.01f * v01;
                v10 = (v10 > 0.f) ? v10 : 0.01f * v10;
                v11 = (v11 > 0.f) ? v11 : 0.01f * v11;
                float h00 = __bfloat162float(__float2bfloat16(v00));
                float h01 = __bfloat162float(__float2bfloat16(v01));
                float h10 = __bfloat162float(__float2bfloat16(v10));
                float h11 = __bfloat162float(__float2bfloat16(v11));
                *(uint32_t*)&Chi[(size_t)r0 * ldc + col] = pack_bf2(v00, v01);
                *(uint32_t*)&Clo[(size_t)r0 * ldc + col] = pack_bf2(v00 - h00, v01 - h01);
                *(uint32_t*)&Chi[(size_t)r1 * ldc + col] = pack_bf2(v10, v11);
                *(uint32_t*)&Clo[(size_t)r1 * ldc + col] = pack_bf2(v10 - h10, v11 - h11);
            }
        }
    }
}

// ================= fused attention logits (HMMA, split 3-pass) =================
// CTA: 64 seq rows; A slab resident; N=512 as 4x128 tiles; warp layout 2M x 4N.
#define SA_HI    0
#define SA_LO    65536
#define SB_OFF   131072
#define UVW_OFF  196608
#define PART_OFF 200704
#define ATT_SMEM 201728

__global__ void __launch_bounds__(256) attn_mma(
    const float* __restrict__ enc,
    const __nv_bfloat16* __restrict__ w1hi, const __nv_bfloat16* __restrict__ w1lo,
    const float* __restrict__ W1b, const float* __restrict__ ug,
    const float* __restrict__ Vw, const float* __restrict__ Vb,
    float* __restrict__ logits)
{
    extern __shared__ __align__(128) char sm[];
    const uint32_t smb = smem_u32(sm);
    const int tid = threadIdx.x, wid = tid >> 5, lane = tid & 31;
    const int m0 = blockIdx.x * 64;
    const int b = blockIdx.x >> 1;
    const int mb = wid & 1, nw = wid >> 1;

    float2* uvw = (float2*)(sm + UVW_OFF);
    for (int n = tid; n < HH; n += 256)
        uvw[n] = make_float2(ug[(size_t)b * 2048 + n] + W1b[n], Vw[n]);

    // A slab: 64 x 512 fp32 -> hi/lo bf16, swizzled (row stride 1024B)
    #pragma unroll
    for (int it = 0; it < 16; it++) {
        int idx = tid + it * 256;
        int r = idx >> 6, c = idx & 63;
        const float4* src = (const float4*)(enc + (size_t)(m0 + r) * HH + c * 8);
        float4 v0 = src[0], v1 = src[1];
        float f[8] = {v0.x, v0.y, v0.z, v0.w, v1.x, v1.y, v1.z, v1.w};
        float h[8], l[8];
        #pragma unroll
        for (int j = 0; j < 8; j++) {
            h[j] = __bfloat162float(__float2bfloat16(f[j]));
            l[j] = f[j] - h[j];
        }
        uint4 hv, lv;
        hv.x = pack_bf2(h[0], h[1]); hv.y = pack_bf2(h[2], h[3]);
        hv.z = pack_bf2(h[4], h[5]); hv.w = pack_bf2(h[6], h[7]);
        lv.x = pack_bf2(l[0], l[1]); lv.y = pack_bf2(l[2], l[3]);
        lv.z = pack_bf2(l[4], l[5]); lv.w = pack_bf2(l[6], l[7]);
        uint32_t off = (uint32_t)(r * 1024 + ((c ^ (r & 7)) << 4));
        *(uint4*)(sm + SA_HI + off) = hv;
        *(uint4*)(sm + SA_LO + off) = lv;
    }
    __syncthreads();

    const int aswz = lane & 7;
    uint32_t aB[2], bB[2];
    #pragma unroll
    for (int f = 0; f < 2; f++) {
        aB[f] = smb + SA_HI + (mb * 32 + f * 16 + (lane & 15)) * 1024;
        bB[f] = smb + SB_OFF + (nw * 32 + f * 16 + (lane & 15)) * 128;
    }

    float acc[2][4][4] = {};
    float rp[4] = {0.f, 0.f, 0.f, 0.f};

    auto prefetch = [&](int itc) {
        int nt = itc >> 3, kc = itc & 7, buf = itc & 1;
        #pragma unroll
        for (int it2 = 0; it2 < 4; it2++) {
            int idx = tid + it2 * 256;
            int r = idx >> 3, c = idx & 7;
            uint32_t dst = smb + SB_OFF + buf * 32768 + r * 128 + ((uint32_t)(c ^ (r & 7)) << 4);
            size_t gofs = (size_t)(nt * 128 + r) * HH + kc * 64 + c * 8;
            cpasync16(dst,         w1hi + gofs);
            cpasync16(dst + 16384, w1lo + gofs);
        }
        CP_COMMIT();
    };

    prefetch(0);

    for (int itc = 0; itc < 32; itc++) {
        const int nt = itc >> 3, kc = itc & 7, buf = itc & 1;
        if (itc < 31) {
            prefetch(itc + 1);
            asm volatile("cp.async.wait_group 1;" ::: "memory");
        } else {
            asm volatile("cp.async.wait_group 0;" ::: "memory");
        }
        __syncthreads();

        #pragma unroll
        for (int ks = 0; ks < 4; ks++) {
            int achunk = kc * 8 + ks * 2 + (lane >> 4);
            uint32_t acoff = (uint32_t)(achunk ^ aswz) << 4;
            int bchunk = ks * 2 + (lane >> 4);
            uint32_t bcoff = (uint32_t)(bchunk ^ aswz) << 4;
            uint32_t ah[2][4], al[2][4], bh[2][4], bl[2][4];
            #pragma unroll
            for (int f = 0; f < 2; f++) {
                ldm_x4(ah[f], aB[f] + acoff);
                ldm_x4(al[f], aB[f] + acoff + 65536);
                ldm_x4(bh[f], bB[f] + buf * 32768 + bcoff);
                ldm_x4(bl[f], bB[f] + buf * 32768 + bcoff + 16384);
            }
            #pragma unroll
            for (int m = 0; m < 2; m++)
                #pragma unroll
                for (int f2 = 0; f2 < 2; f2++)
                    #pragma unroll
                    for (int sel = 0; sel < 2; sel++) {
                        int n8 = f2 * 2 + sel;
                        uint32_t bfh[2] = { bh[f2][sel], bh[f2][sel + 2] };
                        uint32_t bfl[2] = { bl[f2][sel], bl[f2][sel + 2] };
                        mma16816(acc[m][n8], ah[m], bfh);
                        mma16816(acc[m][n8], ah[m], bfl);
                        mma16816(acc[m][n8], al[m], bfh);
                    }
        }
        __syncthreads();

        if (kc == 7) {
            // epilogue for this 128-col N tile
            #pragma unroll
            for (int f = 0; f < 2; f++)
                #pragma unroll
                for (int n8 = 0; n8 < 4; n8++) {
                    int n = nt * 128 + nw * 32 + n8 * 8 + ((lane & 3) << 1);
                    float2 u0 = uvw[n], u1 = uvw[n + 1];
                    rp[f * 2]     += tanh_acc(acc[f][n8][0] + u0.x) * u0.y
                                   + tanh_acc(acc[f][n8][1] + u1.x) * u1.y;
                    rp[f * 2 + 1] += tanh_acc(acc[f][n8][2] + u0.x) * u0.y
                                   + tanh_acc(acc[f][n8][3] + u1.x) * u1.y;
                    acc[f][n8][0] = acc[f][n8][1] = acc[f][n8][2] = acc[f][n8][3] = 0.f;
                }
        }
    }

    // reduce quads then across 4 nw warps
    #pragma unroll
    for (int i = 0; i < 4; i++) {
        rp[i] += __shfl_xor_sync(0xffffffffu, rp[i], 1);
        rp[i] += __shfl_xor_sync(0xffffffffu, rp[i], 2);
    }
    float* part = (float*)(sm + PART_OFF);
    if ((lane & 3) == 0) {
        int rbase = mb * 32 + (lane >> 2);
        part[nw * 64 + rbase]      = rp[0];
        part[nw * 64 + rbase + 8]  = rp[1];
        part[nw * 64 + rbase + 16] = rp[2];
        part[nw * 64 + rbase + 24] = rp[3];
    }
    __syncthreads();
    if (tid < 64)
        logits[m0 + tid] = part[tid] + part[64 + tid] + part[128 + tid] + part[192 + tid] + Vb[0];
}

// ---------------- softmax over S + context vector (emits split bf16) ----------------
__global__ void __launch_bounds__(256) softmax_ctx(
    const float* __restrict__ logits, const float* __restrict__ enc,
    __nv_bfloat16* __restrict__ ginhi, __nv_bfloat16* __restrict__ ginlo)
{
    __shared__ float w[SS];
    __shared__ float red[256];
    const int b = blockIdx.x, tid = threadIdx.x;
    float v = (tid < SS) ? logits[b * SS + tid] : -1e30f;
    red[tid] = v; __syncthreads();
    for (int s = 128; s > 0; s >>= 1) {
        if (tid < s) red[tid] = fmaxf(red[tid], red[tid + s]);
        __syncthreads();
    }
    float mx = red[0]; __syncthreads();
    float e = (tid < SS) ? expf(v - mx) : 0.f;
    red[tid] = e; __syncthreads();
    for (int s = 128; s > 0; s >>= 1) {
        if (tid < s) red[tid] += red[tid + s];
        __syncthreads();
    }
    float inv = 1.f / red[0];
    if (tid < SS) w[tid] = e * inv;
    __syncthreads();

    const float* encb = enc + (size_t)b * SS * HH;
    for (int h = tid; h < HH; h += 256) {
        float acc = 0.f;
        #pragma unroll 4
        for (int s = 0; s < SS; s++)
            acc += w[s] * encb[s * HH + h];
        __nv_bfloat16 hi, lo; split2(acc, hi, lo);
        ginhi[(size_t)b * KIH + h] = hi;
        ginlo[(size_t)b * KIH + h] = lo;
    }
}

// ---------------- embedding gather into gin[:, H:H+320] (split bf16, pads) ----------------
__global__ void emb_gather(const int* __restrict__ x,
                           const float* __restrict__ emb_table,
                           __nv_bfloat16* __restrict__ ginhi,
                           __nv_bfloat16* __restrict__ ginlo)
{
    int i = blockIdx.x * blockDim.x + threadIdx.x;
    if (i >= BB * 320) return;
    int b = i / 320, e = i - b * 320;
    float v = (e < EE) ? emb_table[(size_t)x[b] * EE + e] : 0.f;
    __nv_bfloat16 hi, lo; split2(v, hi, lo);
    size_t o = (size_t)b * KIH + HH + e;
    ginhi[o] = hi; ginlo[o] = lo;
}

// ---------------- GRU pointwise (emits h_out f32 + hnew split bf16) ----------------
__global__ void gru_pointwise(const float* __restrict__ gi,
                              const float* __restrict__ ug,
                              const float* __restrict__ h0,
                              float* __restrict__ hout,
                              __nv_bfloat16* __restrict__ hnhi,
                              __nv_bfloat16* __restrict__ hnlo)
{
    int i = blockIdx.x * blockDim.x + threadIdx.x;
    if (i >= BB * HH) return;
    int b = i / HH, h = i - b * HH;
    size_t gib = (size_t)b * H3 + h;
    size_t ghb = (size_t)b * 2048 + 512 + h;
    float i_r = gi[gib], i_z = gi[gib + HH], i_n = gi[gib + 2 * HH];
    float h_r = ug[ghb], h_z = ug[ghb + HH], h_n = ug[ghb + 2 * HH];
    float r = 1.f / (1.f + expf(-(i_r + h_r)));
    float z = 1.f / (1.f + expf(-(i_z + h_z)));
    float n = tanhf(i_n + r * h_n);
    float hn = (1.f - z) * n + z * h0[i];
    hout[i] = hn;
    __nv_bfloat16 hi, lo; split2(hn, hi, lo);
    hnhi[i] = hi; hnlo[i] = lo;
}

// ---------------- launch ----------------
extern "C" void kernel_launch(void* const* d_in, const int* in_sizes, int n_in,
                              void* d_out, int out_size)
{
    const int*   x        = (const int*)  d_in[0];
    const float* hidden   = (const float*)d_in[1];
    const float* enc      = (const float*)d_in[2];
    const float* emb_t    = (const float*)d_in[3];
    const float* W1_w     = (const float*)d_in[4];
    const float* W1_b     = (const float*)d_in[5];
    const float* W2_w     = (const float*)d_in[6];
    const float* W2_b     = (const float*)d_in[7];
    const float* V_w      = (const float*)d_in[8];
    const float* V_b      = (const float*)d_in[9];
    const float* gru_w_ih = (const float*)d_in[10];
    const float* gru_w_hh = (const float*)d_in[11];
    const float* gru_b_ih = (const float*)d_in[12];
    const float* gru_b_hh = (const float*)d_in[13];
    const float* fc1_w    = (const float*)d_in[14];
    const float* fc1_b    = (const float*)d_in[15];
    const float* fc2_w    = (const float*)d_in[16];
    const float* fc2_b    = (const float*)d_in[17];

    float* y_out = (float*)d_out;
    float* h_out = y_out + (size_t)BB * VV;

    float *p_ug, *p_gi, *p_logits, *p_bc, *p_bfc1;
    __nv_bfloat16 *p_hidh, *p_hidl, *p_wch, *p_wcl, *p_w1h, *p_w1l;
    __nv_bfloat16 *p_wihh, *p_wihl, *p_ginh, *p_ginl, *p_hnh, *p_hnl;
    __nv_bfloat16 *p_f1h, *p_f1l, *p_f2h, *p_f2l, *p_a1h, *p_a1l;
    cudaGetSymbolAddress((void**)&p_ug, g_ug);
    cudaGetSymbolAddress((void**)&p_gi, g_gi);
    cudaGetSymbolAddress((void**)&p_logits, g_logits);
    cudaGetSymbolAddress((void**)&p_bc, g_bc);
    cudaGetSymbolAddress((void**)&p_bfc1, g_bfc1);
    cudaGetSymbolAddress((void**)&p_hidh, g_hid_hi);  cudaGetSymbolAddress((void**)&p_hidl, g_hid_lo);
    cudaGetSymbolAddress((void**)&p_wch, g_wc_hi);    cudaGetSymbolAddress((void**)&p_wcl, g_wc_lo);
    cudaGetSymbolAddress((void**)&p_w1h, g_w1hi);     cudaGetSymbolAddress((void**)&p_w1l, g_w1lo);
    cudaGetSymbolAddress((void**)&p_wihh, g_wih_hi);  cudaGetSymbolAddress((void**)&p_wihl, g_wih_lo);
    cudaGetSymbolAddress((void**)&p_ginh, g_gin_hi);  cudaGetSymbolAddress((void**)&p_ginl, g_gin_lo);
    cudaGetSymbolAddress((void**)&p_hnh, g_hn_hi);    cudaGetSymbolAddress((void**)&p_hnl, g_hn_lo);
    cudaGetSymbolAddress((void**)&p_f1h, g_fc1_hi);   cudaGetSymbolAddress((void**)&p_f1l, g_fc1_lo);
    cudaGetSymbolAddress((void**)&p_f2h, g_fc2_hi);   cudaGetSymbolAddress((void**)&p_f2l, g_fc2_lo);
    cudaGetSymbolAddress((void**)&p_a1h, g_a1_hi);    cudaGetSymbolAddress((void**)&p_a1l, g_a1_lo);

    cudaFuncSetAttribute(attn_mma, cudaFuncAttributeMaxDynamicSharedMemorySize, ATT_SMEM);
    cudaFuncSetAttribute(hgemm_bt_mma<0>, cudaFuncAttributeMaxDynamicSharedMemorySize, HG_SMEM);
    cudaFuncSetAttribute(hgemm_bt_mma<1>, cudaFuncAttributeMaxDynamicSharedMemorySize, HG_SMEM);

    // ---- prep: weight/activation splits + bias pads ----
    split_pad<<<(512 * 512 + 255) / 256, 256>>>(W2_w, 512, 512, p_wch, p_wcl, 512, 512, 0);
    split_pad<<<(1536 * 512 + 255) / 256, 256>>>(gru_w_hh, 1536, 512, p_wch, p_wcl, 1536, 512, 512);
    split_pad<<<(2048 * 512 + 255) / 256, 256>>>(hidden, 2048, 512, p_hidh, p_hidl, 2048, 512, 0);
    split_pad<<<(512 * 512 + 255) / 256, 256>>>(W1_w, 512, 512, p_w1h, p_w1l, 512, 512, 0);
    split_pad<<<(1536 * KIH + 255) / 256, 256>>>(gru_w_ih, 1536, 812, p_wihh, p_wihl, 1536, KIH, 0);
    split_pad<<<(KF * 512 + 255) / 256, 256>>>(fc1_w, 300, 512, p_f1h, p_f1l, KF, 512, 0);
    split_pad<<<(VV * KF + 255) / 256, 256>>>(fc2_w, 128, 300, p_f2h, p_f2l, VV, KF, 0);
    pad_bias<<<2, 256>>>(W2_b, 512, p_bc, 512, 0);
    pad_bias<<<6, 256>>>(gru_b_hh, 1536, p_bc, 1536, 512);
    pad_bias<<<2, 256>>>(fc1_b, 300, p_bfc1, KF, 0);

    // ---- ug = h0 @ [W2; gru_w_hh]^T + [W2_b; gru_b_hh] : [2048 x 2048] ----
    hgemm_bt_mma<0><<<dim3(2048 / 128, BB / 64), 256, HG_SMEM>>>(
        p_hidh, p_hidl, p_wch, p_wcl, p_bc, p_ug, nullptr, nullptr, 512, 512, 2048);
    // ---- attention logits ----
    attn_mma<<<BB * 2, 256, ATT_SMEM>>>(enc, p_w1h, p_w1l, W1_b, p_ug, V_w, V_b, p_logits);
    // ---- softmax + ctx -> gin hi/lo ----
    softmax_ctx<<<BB, 256>>>(p_logits, enc, p_ginh, p_ginl);
    emb_gather<<<(BB * 320 + 255) / 256, 256>>>(x, emb_t, p_ginh, p_ginl);
    // ---- gi = gin @ gru_w_ih^T + gru_b_ih : [2048 x 1536], K=832 ----
    hgemm_bt_mma<0><<<dim3(H3 / 128, BB / 64), 256, HG_SMEM>>>(
        p_ginh, p_ginl, p_wihh, p_wihl, gru_b_ih, p_gi, nullptr, nullptr, KIH, KIH, H3);
    // ---- GRU pointwise ----
    gru_pointwise<<<(BB * HH + 255) / 256, 256>>>(p_gi, p_ug, hidden, h_out, p_hnh, p_hnl);
    // ---- a1 = leaky_relu(hnew @ fc1^T + b) -> split bf16 [2048 x 384] ----
    hgemm_bt_mma<1><<<dim3(KF / 128, BB / 64), 256, HG_SMEM>>>(
        p_hnh, p_hnl, p_f1h, p_f1l, p_bfc1, nullptr, p_a1h, p_a1l, 512, 512, KF);
    // ---- y = a1 @ fc2^T + fc2_b : [2048 x 128], K=384 ----
    hgemm_bt_mma<0><<<dim3(VV / 128, BB / 64), 256, HG_SMEM>>>(
        p_a1h, p_a1l, p_f2h, p_f2l, fc2_b, y_out, nullptr, nullptr, KF, KF, VV);
}

// round 10
// speedup vs baseline: 5.8818x; 1.5488x over previous
#include <cuda_runtime.h>
#include <cuda_fp16.h>
#include <math.h>
#include <stdint.h>

// Problem dims
#define BB 2048
#define SS 128
#define VV 128
#define EE 300
#define HH 512
#define H3 1536
#define KIH 832              // padded 812
#define KF  384              // fc1-out / fc2-K padding

// ---------------- scratch (device globals) ----------------
__device__ float  g_ug[BB * 2048];           // [u | gh]
__device__ float  g_gi[BB * H3];
__device__ __half g_hid_h[BB * HH];
__device__ __half g_wc_hi[2048 * HH], g_wc_lo[2048 * HH];   // [W2; gru_w_hh]
__device__ __half g_w1_hi[HH * HH],   g_w1_lo[HH * HH];
__device__ __half g_wih_hi[H3 * KIH], g_wih_lo[H3 * KIH];
__device__ __half g_gin_h[BB * KIH];
__device__ __half g_hn_h[BB * HH];
__device__ __half g_f1_hi[KF * HH],  g_f1_lo[KF * HH];
__device__ __half g_f2_hi[VV * KF],  g_f2_lo[VV * KF];
__device__ __half g_a1_h[BB * KF];
__device__ float  g_bc[2048];
__device__ float  g_bfc1[KF];

// ================= helpers =================
__device__ __forceinline__ uint32_t smem_u32(const void* p) {
    uint32_t a;
    asm("{ .reg .u64 t; cvta.to.shared.u64 t, %1; cvt.u32.u64 %0, t; }" : "=r"(a) : "l"(p));
    return a;
}
__device__ __forceinline__ void ldm_x4(uint32_t* r, uint32_t addr) {
    asm volatile("ldmatrix.sync.aligned.m8n8.x4.shared.b16 {%0,%1,%2,%3}, [%4];"
        : "=r"(r[0]), "=r"(r[1]), "=r"(r[2]), "=r"(r[3]) : "r"(addr));
}
__device__ __forceinline__ void mma_h(float* c, const uint32_t* a, const uint32_t* b) {
    asm volatile("mma.sync.aligned.m16n8k16.row.col.f32.f16.f16.f32 "
        "{%0,%1,%2,%3}, {%4,%5,%6,%7}, {%8,%9}, {%0,%1,%2,%3};"
        : "+f"(c[0]), "+f"(c[1]), "+f"(c[2]), "+f"(c[3])
        : "r"(a[0]), "r"(a[1]), "r"(a[2]), "r"(a[3]), "r"(b[0]), "r"(b[1]));
}
__device__ __forceinline__ void cpasync16(uint32_t dst, const void* src) {
    asm volatile("cp.async.cg.shared.global [%0], [%1], 16;" :: "r"(dst), "l"(src) : "memory");
}
#define CP_COMMIT() asm volatile("cp.async.commit_group;" ::: "memory")

__device__ __forceinline__ uint32_t pack_h2(float a, float b) {
    __half2 t = __floats2half2_rn(a, b);
    return *(uint32_t*)&t;
}
__device__ __forceinline__ float tanh_acc(float x) {
    x = fminf(fmaxf(x, -15.f), 15.f);
    float e = __expf(2.f * x);
    return __fdividef(e - 1.f, e + 1.f);
}

// ================= prep kernels =================
// weights: fp16 hi + lo (lo = residual)
__global__ void split_pad_hl(const float* __restrict__ src, int R, int C,
                             __half* __restrict__ hi, __half* __restrict__ lo,
                             int Rp, int Cp, int rowOff)
{
    int i = blockIdx.x * 256 + threadIdx.x;
    if (i >= Rp * Cp) return;
    int r = i / Cp, c = i - r * Cp;
    float v = (r < R && c < C) ? src[(size_t)r * C + c] : 0.f;
    __half h = __float2half_rn(v);
    size_t o = (size_t)(r + rowOff) * Cp + c;
    hi[o] = h;
    lo[o] = __float2half_rn(v - __half2float(h));
}
// activations: single fp16
__global__ void cvt_h(const float* __restrict__ src, __half* __restrict__ dst, int n) {
    int i = blockIdx.x * 256 + threadIdx.x;
    if (i < n) dst[i] = __float2half_rn(src[i]);
}
__global__ void pad_bias(const float* __restrict__ src, int n,
                         float* __restrict__ dst, int np, int off)
{
    int i = blockIdx.x * 256 + threadIdx.x;
    if (i < np) dst[off + i] = (i < n) ? src[i] : 0.f;
}

// ================= HMMA fp16 2-pass GEMM =================
// C[M,N] = A[M,K] @ (Bhi+Blo)[N,K]^T + bias ; A single fp16, B split fp16.
// CTA 64M x 128N, 8 warps 2M x 4N (warp tile 32x32).
// OUT=0: fp32 C ; OUT=1: leaky_relu -> fp16 Ch
#define HG_BUF  40960           // A 8K | Bhi 16K | Blo 16K
#define HG_SMEM 81920
template<int OUT>
__global__ void __launch_bounds__(256) hgemm(
    const __half* __restrict__ A,
    const __half* __restrict__ Bhi, const __half* __restrict__ Blo,
    const float* __restrict__ bias, float* __restrict__ C,
    __half* __restrict__ Ch, int K, int lda, int ldc)
{
    extern __shared__ __align__(128) char sm[];
    const uint32_t smb = smem_u32(sm);
    const int tid = threadIdx.x, wid = tid >> 5, lane = tid & 31;
    const int mb = wid & 1, nw = wid >> 1;
    const int m0 = blockIdx.y * 64, n0 = blockIdx.x * 128;
    const int nk = K >> 6;

    auto prefetch = [&](int kc) {
        uint32_t base = smb + (uint32_t)(kc & 1) * HG_BUF;
        #pragma unroll
        for (int it = 0; it < 2; it++) {                 // A: 64 rows x 8 chunks
            int idx = tid + it * 256;
            int r = idx >> 3, c = idx & 7;
            uint32_t dst = base + r * 128 + ((uint32_t)(c ^ (r & 7)) << 4);
            cpasync16(dst, A + (size_t)(m0 + r) * lda + kc * 64 + c * 8);
        }
        #pragma unroll
        for (int it = 0; it < 4; it++) {                 // B: 128 rows x 8 chunks, hi+lo
            int idx = tid + it * 256;
            int r = idx >> 3, c = idx & 7;
            uint32_t dst = base + 8192 + r * 128 + ((uint32_t)(c ^ (r & 7)) << 4);
            size_t go = (size_t)(n0 + r) * K + kc * 64 + c * 8;
            cpasync16(dst,         Bhi + go);
            cpasync16(dst + 16384, Blo + go);
        }
        CP_COMMIT();
    };

    float acc[2][4][4] = {};
    const int aswz = lane & 7;
    prefetch(0);

    for (int kc = 0; kc < nk; kc++) {
        if (kc + 1 < nk) {
            prefetch(kc + 1);
            asm volatile("cp.async.wait_group 1;" ::: "memory");
        } else {
            asm volatile("cp.async.wait_group 0;" ::: "memory");
        }
        __syncthreads();
        uint32_t base = smb + (uint32_t)(kc & 1) * HG_BUF;
        uint32_t aB[2], bB[2];
        #pragma unroll
        for (int f = 0; f < 2; f++) {
            aB[f] = base + (mb * 32 + f * 16 + (lane & 15)) * 128;
            bB[f] = base + 8192 + (nw * 32 + f * 16 + (lane & 15)) * 128;
        }
        #pragma unroll
        for (int ks = 0; ks < 4; ks++) {
            int chunk = ks * 2 + (lane >> 4);
            uint32_t coff = (uint32_t)(chunk ^ aswz) << 4;
            uint32_t ah[2][4], bh[2][4], bl[2][4];
            #pragma unroll
            for (int f = 0; f < 2; f++) {
                ldm_x4(ah[f], aB[f] + coff);
                ldm_x4(bh[f], bB[f] + coff);
                ldm_x4(bl[f], bB[f] + coff + 16384);
            }
            #pragma unroll
            for (int m = 0; m < 2; m++)
                #pragma unroll
                for (int f2 = 0; f2 < 2; f2++)
                    #pragma unroll
                    for (int sel = 0; sel < 2; sel++) {
                        int n8 = f2 * 2 + sel;
                        uint32_t bfh[2] = { bh[f2][sel], bh[f2][sel + 2] };
                        uint32_t bfl[2] = { bl[f2][sel], bl[f2][sel + 2] };
                        mma_h(acc[m][n8], ah[m], bfh);
                        mma_h(acc[m][n8], ah[m], bfl);
                    }
        }
        __syncthreads();
    }

    #pragma unroll
    for (int f = 0; f < 2; f++) {
        int r0 = m0 + mb * 32 + f * 16 + (lane >> 2);
        int r1 = r0 + 8;
        #pragma unroll
        for (int n8 = 0; n8 < 4; n8++) {
            int col = n0 + nw * 32 + n8 * 8 + ((lane & 3) << 1);
            float b0 = bias[col], b1 = bias[col + 1];
            float v00 = acc[f][n8][0] + b0, v01 = acc[f][n8][1] + b1;
            float v10 = acc[f][n8][2] + b0, v11 = acc[f][n8][3] + b1;
            if (OUT == 0) {
                *(float2*)&C[(size_t)r0 * ldc + col] = make_float2(v00, v01);
                *(float2*)&C[(size_t)r1 * ldc + col] = make_float2(v10, v11);
            } else {
                v00 = (v00 > 0.f) ? v00 : 0.01f * v00;
                v01 = (v01 > 0.f) ? v01 : 0.01f * v01;
                v10 = (v10 > 0.f) ? v10 : 0.01f * v10;
                v11 = (v11 > 0.f) ? v11 : 0.01f * v11;
                *(uint32_t*)&Ch[(size_t)r0 * ldc + col] = pack_h2(v00, v01);
                *(uint32_t*)&Ch[(size_t)r1 * ldc + col] = pack_h2(v10, v11);
            }
        }
    }
}

// ================= fused attention: logits + softmax + ctx =================
// CTA = 128 seq rows = one batch b. A slab (128x512 fp16) resident in smem.
// B = W1 hi/lo streamed; 2-pass fp16 MMA. After logits: in-CTA softmax and
// ctx = attw @ enc (from the resident fp16 slab) -> gin fp16.
#define SA       0          // 128 x 1024 B = 131072
#define SB       131072     // 2 bufs x (hi 16K + lo 16K) = 65536
#define UVW_OFF  196608     // float2[512]
#define PART_OFF 200704     // float[512]
#define SW_OFF   202752     // float[128]
#define RED_OFF  203264     // float[256]
#define ATT_SMEM 204288

__global__ void __launch_bounds__(256) attn_fused(
    const float* __restrict__ enc,
    const __half* __restrict__ w1hi, const __half* __restrict__ w1lo,
    const float* __restrict__ W1b, const float* __restrict__ ug,
    const float* __restrict__ Vw, const float* __restrict__ Vb,
    __half* __restrict__ ginh)
{
    extern __shared__ __align__(128) char sm[];
    const uint32_t smb = smem_u32(sm);
    const int tid = threadIdx.x, wid = tid >> 5, lane = tid & 31;
    const int b = blockIdx.x;
    const int mb = wid & 1, nw = wid >> 1;

    float2* uvw = (float2*)(sm + UVW_OFF);
    for (int n = tid; n < HH; n += 256)
        uvw[n] = make_float2(ug[(size_t)b * 2048 + n] + W1b[n], Vw[n]);

    // A slab: 128 x 512 fp32 -> fp16, swizzled (row stride 1024 B)
    #pragma unroll 4
    for (int it = 0; it < 32; it++) {
        int idx = tid + it * 256;           // 0..8191 chunks (16B)
        int r = idx >> 6, c = idx & 63;
        const float4* src = (const float4*)(enc + (size_t)(b * SS + r) * HH + c * 8);
        float4 v0 = src[0], v1 = src[1];
        uint4 hv;
        hv.x = pack_h2(v0.x, v0.y); hv.y = pack_h2(v0.z, v0.w);
        hv.z = pack_h2(v1.x, v1.y); hv.w = pack_h2(v1.z, v1.w);
        uint32_t off = (uint32_t)(r * 1024 + ((c ^ (r & 7)) << 4));
        *(uint4*)(sm + SA + off) = hv;
    }
    __syncthreads();

    const int aswz = lane & 7;
    uint32_t aB[4], bB[2];
    #pragma unroll
    for (int f = 0; f < 4; f++)
        aB[f] = smb + SA + (mb * 64 + f * 16 + (lane & 15)) * 1024;
    #pragma unroll
    for (int f2 = 0; f2 < 2; f2++)
        bB[f2] = smb + SB + (nw * 32 + f2 * 16 + (lane & 15)) * 128;

    float acc[4][4][4] = {};
    float rp[8] = {};

    auto prefetch = [&](int itc) {
        int nt = itc >> 3, kc = itc & 7, buf = itc & 1;
        #pragma unroll
        for (int it2 = 0; it2 < 4; it2++) {
            int idx = tid + it2 * 256;
            int r = idx >> 3, c = idx & 7;
            uint32_t dst = smb + SB + buf * 32768 + r * 128 + ((uint32_t)(c ^ (r & 7)) << 4);
            size_t gofs = (size_t)(nt * 128 + r) * HH + kc * 64 + c * 8;
            cpasync16(dst,         w1hi + gofs);
            cpasync16(dst + 16384, w1lo + gofs);
        }
        CP_COMMIT();
    };

    prefetch(0);

    for (int itc = 0; itc < 32; itc++) {
        const int nt = itc >> 3, kc = itc & 7, buf = itc & 1;
        if (itc < 31) {
            prefetch(itc + 1);
            asm volatile("cp.async.wait_group 1;" ::: "memory");
        } else {
            asm volatile("cp.async.wait_group 0;" ::: "memory");
        }
        __syncthreads();

        #pragma unroll
        for (int ks = 0; ks < 4; ks++) {
            int achunk = kc * 8 + ks * 2 + (lane >> 4);
            uint32_t acoff = (uint32_t)(achunk ^ aswz) << 4;
            int bchunk = ks * 2 + (lane >> 4);
            uint32_t bcoff = (uint32_t)(bchunk ^ aswz) << 4;
            uint32_t ah[4][4], bh[2][4], bl[2][4];
            #pragma unroll
            for (int f = 0; f < 4; f++) ldm_x4(ah[f], aB[f] + acoff);
            #pragma unroll
            for (int f2 = 0; f2 < 2; f2++) {
                ldm_x4(bh[f2], bB[f2] + buf * 32768 + bcoff);
                ldm_x4(bl[f2], bB[f2] + buf * 32768 + bcoff + 16384);
            }
            #pragma unroll
            for (int f = 0; f < 4; f++)
                #pragma unroll
                for (int f2 = 0; f2 < 2; f2++)
                    #pragma unroll
                    for (int sel = 0; sel < 2; sel++) {
                        int n8 = f2 * 2 + sel;
                        uint32_t bfh[2] = { bh[f2][sel], bh[f2][sel + 2] };
                        uint32_t bfl[2] = { bl[f2][sel], bl[f2][sel + 2] };
                        mma_h(acc[f][n8], ah[f], bfh);
                        mma_h(acc[f][n8], ah[f], bfl);
                    }
        }
        __syncthreads();

        if (kc == 7) {
            #pragma unroll
            for (int f = 0; f < 4; f++)
                #pragma unroll
                for (int n8 = 0; n8 < 4; n8++) {
                    int n = nt * 128 + nw * 32 + n8 * 8 + ((lane & 3) << 1);
                    float2 u0 = uvw[n], u1 = uvw[n + 1];
                    rp[f * 2]     += tanh_acc(acc[f][n8][0] + u0.x) * u0.y
                                   + tanh_acc(acc[f][n8][1] + u1.x) * u1.y;
                    rp[f * 2 + 1] += tanh_acc(acc[f][n8][2] + u0.x) * u0.y
                                   + tanh_acc(acc[f][n8][3] + u1.x) * u1.y;
                    acc[f][n8][0] = acc[f][n8][1] = acc[f][n8][2] = acc[f][n8][3] = 0.f;
                }
        }
    }

    // quad reduce (lanes sharing a row)
    #pragma unroll
    for (int i = 0; i < 8; i++) {
        rp[i] += __shfl_xor_sync(0xffffffffu, rp[i], 1);
        rp[i] += __shfl_xor_sync(0xffffffffu, rp[i], 2);
    }
    float* part = (float*)(sm + PART_OFF);
    if ((lane & 3) == 0) {
        #pragma unroll
        for (int f = 0; f < 4; f++) {
            int row = mb * 64 + f * 16 + (lane >> 2);
            part[nw * 128 + row]     = rp[f * 2];
            part[nw * 128 + row + 8] = rp[f * 2 + 1];
        }
    }
    __syncthreads();

    // logits + softmax (128 values)
    float* w   = (float*)(sm + SW_OFF);
    float* red = (float*)(sm + RED_OFF);
    float lg = -1e30f;
    if (tid < 128)
        lg = part[tid] + part[128 + tid] + part[256 + tid] + part[384 + tid] + Vb[0];
    red[tid] = lg;
    __syncthreads();
    for (int s = 128; s > 0; s >>= 1) {
        if (tid < s) red[tid] = fmaxf(red[tid], red[tid + s]);
        __syncthreads();
    }
    float mx = red[0];
    __syncthreads();
    float e = (tid < 128) ? __expf(lg - mx) : 0.f;
    red[tid] = e;
    __syncthreads();
    for (int s = 128; s > 0; s >>= 1) {
        if (tid < s) red[tid] += red[tid + s];
        __syncthreads();
    }
    float inv = 1.f / red[0];
    if (tid < 128) w[tid] = e * inv;
    __syncthreads();

    // ctx from resident fp16 slab: thread -> cols (2*tid, 2*tid+1)
    {
        int h0 = tid * 2;
        int chunk = h0 >> 3;
        uint32_t byte_in = (uint32_t)(h0 & 7) * 2;
        float c0 = 0.f, c1 = 0.f;
        #pragma unroll 8
        for (int s = 0; s < SS; s++) {
            float ws = w[s];
            uint32_t addr = (uint32_t)(s * 1024 + (((uint32_t)(chunk ^ (s & 7))) << 4) + byte_in);
            __half2 hv = *(__half2*)(sm + SA + addr);
            float2 f2v = __half22float2(hv);
            c0 = fmaf(ws, f2v.x, c0);
            c1 = fmaf(ws, f2v.y, c1);
        }
        *(uint32_t*)&ginh[(size_t)b * KIH + h0] = pack_h2(c0, c1);
    }
}

// ---------------- embedding gather into gin[:, 512:832] (fp16, pads) ----------------
__global__ void emb_gather(const int* __restrict__ x,
                           const float* __restrict__ emb_table,
                           __half* __restrict__ ginh)
{
    int i = blockIdx.x * blockDim.x + threadIdx.x;
    if (i >= BB * 320) return;
    int b = i / 320, e = i - b * 320;
    float v = (e < EE) ? emb_table[(size_t)x[b] * EE + e] : 0.f;
    ginh[(size_t)b * KIH + HH + e] = __float2half_rn(v);
}

// ---------------- GRU pointwise ----------------
__global__ void gru_pointwise(const float* __restrict__ gi,
                              const float* __restrict__ ug,
                              const float* __restrict__ h0,
                              float* __restrict__ hout,
                              __half* __restrict__ hnh)
{
    int i = blockIdx.x * blockDim.x + threadIdx.x;
    if (i >= BB * HH) return;
    int b = i / HH, h = i - b * HH;
    size_t gib = (size_t)b * H3 + h;
    size_t ghb = (size_t)b * 2048 + 512 + h;
    float i_r = gi[gib], i_z = gi[gib + HH], i_n = gi[gib + 2 * HH];
    float h_r = ug[ghb], h_z = ug[ghb + HH], h_n = ug[ghb + 2 * HH];
    float r = 1.f / (1.f + expf(-(i_r + h_r)));
    float z = 1.f / (1.f + expf(-(i_z + h_z)));
    float n = tanhf(i_n + r * h_n);
    float hn = (1.f - z) * n + z * h0[i];
    hout[i] = hn;
    hnh[i] = __float2half_rn(hn);
}

// ---------------- launch ----------------
extern "C" void kernel_launch(void* const* d_in, const int* in_sizes, int n_in,
                              void* d_out, int out_size)
{
    const int*   x        = (const int*)  d_in[0];
    const float* hidden   = (const float*)d_in[1];
    const float* enc      = (const float*)d_in[2];
    const float* emb_t    = (const float*)d_in[3];
    const float* W1_w     = (const float*)d_in[4];
    const float* W1_b     = (const float*)d_in[5];
    const float* W2_w     = (const float*)d_in[6];
    const float* W2_b     = (const float*)d_in[7];
    const float* V_w      = (const float*)d_in[8];
    const float* V_b      = (const float*)d_in[9];
    const float* gru_w_ih = (const float*)d_in[10];
    const float* gru_w_hh = (const float*)d_in[11];
    const float* gru_b_ih = (const float*)d_in[12];
    const float* gru_b_hh = (const float*)d_in[13];
    const float* fc1_w    = (const float*)d_in[14];
    const float* fc1_b    = (const float*)d_in[15];
    const float* fc2_w    = (const float*)d_in[16];
    const float* fc2_b    = (const float*)d_in[17];

    float* y_out = (float*)d_out;
    float* h_out = y_out + (size_t)BB * VV;

    float *p_ug, *p_gi, *p_bc, *p_bfc1;
    __half *p_hid, *p_wch, *p_wcl, *p_w1h, *p_w1l, *p_wihh, *p_wihl;
    __half *p_gin, *p_hn, *p_f1h, *p_f1l, *p_f2h, *p_f2l, *p_a1;
    cudaGetSymbolAddress((void**)&p_ug, g_ug);
    cudaGetSymbolAddress((void**)&p_gi, g_gi);
    cudaGetSymbolAddress((void**)&p_bc, g_bc);
    cudaGetSymbolAddress((void**)&p_bfc1, g_bfc1);
    cudaGetSymbolAddress((void**)&p_hid, g_hid_h);
    cudaGetSymbolAddress((void**)&p_wch, g_wc_hi);   cudaGetSymbolAddress((void**)&p_wcl, g_wc_lo);
    cudaGetSymbolAddress((void**)&p_w1h, g_w1_hi);   cudaGetSymbolAddress((void**)&p_w1l, g_w1_lo);
    cudaGetSymbolAddress((void**)&p_wihh, g_wih_hi); cudaGetSymbolAddress((void**)&p_wihl, g_wih_lo);
    cudaGetSymbolAddress((void**)&p_gin, g_gin_h);
    cudaGetSymbolAddress((void**)&p_hn, g_hn_h);
    cudaGetSymbolAddress((void**)&p_f1h, g_f1_hi);   cudaGetSymbolAddress((void**)&p_f1l, g_f1_lo);
    cudaGetSymbolAddress((void**)&p_f2h, g_f2_hi);   cudaGetSymbolAddress((void**)&p_f2l, g_f2_lo);
    cudaGetSymbolAddress((void**)&p_a1, g_a1_h);

    cudaFuncSetAttribute(attn_fused, cudaFuncAttributeMaxDynamicSharedMemorySize, ATT_SMEM);
    cudaFuncSetAttribute(hgemm<0>, cudaFuncAttributeMaxDynamicSharedMemorySize, HG_SMEM);
    cudaFuncSetAttribute(hgemm<1>, cudaFuncAttributeMaxDynamicSharedMemorySize, HG_SMEM);

    // ---- prep ----
    split_pad_hl<<<(512 * 512 + 255) / 256, 256>>>(W2_w, 512, 512, p_wch, p_wcl, 512, 512, 0);
    split_pad_hl<<<(1536 * 512 + 255) / 256, 256>>>(gru_w_hh, 1536, 512, p_wch, p_wcl, 1536, 512, 512);
    split_pad_hl<<<(512 * 512 + 255) / 256, 256>>>(W1_w, 512, 512, p_w1h, p_w1l, 512, 512, 0);
    split_pad_hl<<<(1536 * KIH + 255) / 256, 256>>>(gru_w_ih, 1536, 812, p_wihh, p_wihl, 1536, KIH, 0);
    split_pad_hl<<<(KF * 512 + 255) / 256, 256>>>(fc1_w, 300, 512, p_f1h, p_f1l, KF, 512, 0);
    split_pad_hl<<<(VV * KF + 255) / 256, 256>>>(fc2_w, 128, 300, p_f2h, p_f2l, VV, KF, 0);
    cvt_h<<<(BB * HH + 255) / 256, 256>>>(hidden, p_hid, BB * HH);
    pad_bias<<<2, 256>>>(W2_b, 512, p_bc, 512, 0);
    pad_bias<<<6, 256>>>(gru_b_hh, 1536, p_bc, 1536, 512);
    pad_bias<<<2, 256>>>(fc1_b, 300, p_bfc1, KF, 0);

    // ---- ug = h0 @ [W2; gru_w_hh]^T + bias : [2048 x 2048] ----
    hgemm<0><<<dim3(2048 / 128, BB / 64), 256, HG_SMEM>>>(
        p_hid, p_wch, p_wcl, p_bc, p_ug, nullptr, 512, 512, 2048);
    // ---- attention: logits + softmax + ctx (fused) -> gin[:, :512] ----
    attn_fused<<<BB, 256, ATT_SMEM>>>(enc, p_w1h, p_w1l, W1_b, p_ug, V_w, V_b, p_gin);
    // ---- emb -> gin[:, 512:832] ----
    emb_gather<<<(BB * 320 + 255) / 256, 256>>>(x, emb_t, p_gin);
    // ---- gi = gin @ gru_w_ih^T + gru_b_ih : [2048 x 1536], K=832 ----
    hgemm<0><<<dim3(H3 / 128, BB / 64), 256, HG_SMEM>>>(
        p_gin, p_wihh, p_wihl, gru_b_ih, p_gi, nullptr, KIH, KIH, H3);
    // ---- GRU pointwise ----
    gru_pointwise<<<(BB * HH + 255) / 256, 256>>>(p_gi, p_ug, hidden, h_out, p_hn);
    // ---- a1 = leaky_relu(hnew @ fc1^T + b) -> fp16 [2048 x 384] ----
    hgemm<1><<<dim3(KF / 128, BB / 64), 256, HG_SMEM>>>(
        p_hn, p_f1h, p_f1l, p_bfc1, nullptr, p_a1, 512, 512, KF);
    // ---- y = a1 @ fc2^T + fc2_b : [2048 x 128], K=384 ----
    hgemm<0><<<dim3(VV / 128, BB / 64), 256, HG_SMEM>>>(
        p_a1, p_f2h, p_f2l, fc2_b, y_out, nullptr, KF, KF, VV);
}

// round 11
// speedup vs baseline: 6.0854x; 1.0346x over previous
#include <cuda_runtime.h>
#include <cuda_fp16.h>
#include <math.h>
#include <stdint.h>

// Problem dims
#define BB 2048
#define SS 128
#define VV 128
#define EE 300
#define HH 512
#define H3 1536
#define KIH 832              // padded 812
#define KF  384              // fc1-out / fc2-K padding

// ---------------- scratch (device globals) ----------------
__device__ float  g_ug[BB * 2048];           // [u | gh]
__device__ float  g_gi[BB * H3];
__device__ __half g_hid_h[BB * HH];
__device__ __half g_wc_hi[2048 * HH], g_wc_lo[2048 * HH];   // [W2; gru_w_hh]
__device__ __half g_w1_hi[HH * HH],   g_w1_lo[HH * HH];
__device__ __half g_wih_hi[H3 * KIH], g_wih_lo[H3 * KIH];
__device__ __half g_gin_h[BB * KIH];
__device__ __half g_hn_h[BB * HH];
__device__ __half g_f1_hi[KF * HH],  g_f1_lo[KF * HH];
__device__ __half g_f2_hi[VV * KF],  g_f2_lo[VV * KF];
__device__ __half g_a1_h[BB * KF];
__device__ float  g_bc[2048];
__device__ float  g_bfc1[KF];

// ================= helpers =================
__device__ __forceinline__ uint32_t smem_u32(const void* p) {
    uint32_t a;
    asm("{ .reg .u64 t; cvta.to.shared.u64 t, %1; cvt.u32.u64 %0, t; }" : "=r"(a) : "l"(p));
    return a;
}
__device__ __forceinline__ void ldm_x4(uint32_t* r, uint32_t addr) {
    asm volatile("ldmatrix.sync.aligned.m8n8.x4.shared.b16 {%0,%1,%2,%3}, [%4];"
        : "=r"(r[0]), "=r"(r[1]), "=r"(r[2]), "=r"(r[3]) : "r"(addr));
}
__device__ __forceinline__ void mma_h(float* c, const uint32_t* a, const uint32_t* b) {
    asm volatile("mma.sync.aligned.m16n8k16.row.col.f32.f16.f16.f32 "
        "{%0,%1,%2,%3}, {%4,%5,%6,%7}, {%8,%9}, {%0,%1,%2,%3};"
        : "+f"(c[0]), "+f"(c[1]), "+f"(c[2]), "+f"(c[3])
        : "r"(a[0]), "r"(a[1]), "r"(a[2]), "r"(a[3]), "r"(b[0]), "r"(b[1]));
}
__device__ __forceinline__ void cpasync16(uint32_t dst, const void* src) {
    asm volatile("cp.async.cg.shared.global [%0], [%1], 16;" :: "r"(dst), "l"(src) : "memory");
}
#define CP_COMMIT() asm volatile("cp.async.commit_group;" ::: "memory")

__device__ __forceinline__ uint32_t pack_h2(float a, float b) {
    __half2 t = __floats2half2_rn(a, b);
    return *(uint32_t*)&t;
}
__device__ __forceinline__ float tanh_fast(float x) {   // HW tanh unit (sm_75+)
    float y;
    asm("tanh.approx.f32 %0, %1;" : "=f"(y) : "f"(x));
    return y;
}
__device__ __forceinline__ float tanh_acc(float x) {    // accurate (~1e-6)
    x = fminf(fmaxf(x, -15.f), 15.f);
    float e = __expf(2.f * x);
    return __fdividef(e - 1.f, e + 1.f);
}
__device__ __forceinline__ float sigmoid_fast(float x) {
    return __fdividef(1.f, 1.f + __expf(-x));
}
__device__ __forceinline__ void split_h(float v, __half& h, __half& l) {
    h = __float2half_rn(v);
    l = __float2half_rn(v - __half2float(h));
}

// ================= prep kernels (merged; ordering matters for ncu -s 5) =================
// 1) W1 split: 512x512
__global__ void prep_w1(const float* __restrict__ w1,
                        __half* __restrict__ hi, __half* __restrict__ lo) {
    int i = blockIdx.x * 256 + threadIdx.x;          // 1024 blocks
    float v = w1[i];
    split_h(v, hi[i], lo[i]);
}
// 2) [W2; gru_w_hh] split: 2048x512
__global__ void prep_wc(const float* __restrict__ w2, const float* __restrict__ whh,
                        __half* __restrict__ hi, __half* __restrict__ lo) {
    int i = blockIdx.x * 256 + threadIdx.x;          // 4096 blocks
    int r = i >> 9;
    float v = (r < 512) ? w2[i] : whh[i - 512 * 512];
    split_h(v, hi[i], lo[i]);
}
// 3) hidden -> fp16
__global__ void cvt_h(const float* __restrict__ src, __half* __restrict__ dst) {
    int i = blockIdx.x * 256 + threadIdx.x;          // 4096 blocks
    dst[i] = __float2half_rn(src[i]);
}
// 4) everything else: wih split (4992 blk) + fc1 (768) + fc2 (192) + biases (10)
#define PR_WIH 4992
#define PR_F1  (PR_WIH + 768)
#define PR_F2  (PR_F1 + 192)
#define PR_BC  (PR_F2 + 8)
#define PR_BF  (PR_BC + 2)
__global__ void prep_rest(const float* __restrict__ wih,
                          const float* __restrict__ fc1w, const float* __restrict__ fc2w,
                          const float* __restrict__ w2b, const float* __restrict__ bhh,
                          const float* __restrict__ f1b,
                          __half* __restrict__ wih_hi, __half* __restrict__ wih_lo,
                          __half* __restrict__ f1_hi,  __half* __restrict__ f1_lo,
                          __half* __restrict__ f2_hi,  __half* __restrict__ f2_lo,
                          float* __restrict__ bc, float* __restrict__ bfc1) {
    int blk = blockIdx.x;
    int t = threadIdx.x;
    if (blk < PR_WIH) {                       // gru_w_ih 1536x812 -> 1536x832
        int i = blk * 256 + t;
        int r = i / KIH, c = i - r * KIH;
        float v = (c < 812) ? wih[(size_t)r * 812 + c] : 0.f;
        split_h(v, wih_hi[i], wih_lo[i]);
    } else if (blk < PR_F1) {                 // fc1_w 300x512 -> 384x512
        int i = (blk - PR_WIH) * 256 + t;
        int r = i >> 9;
        float v = (r < 300) ? fc1w[i] : 0.f;
        split_h(v, f1_hi[i], f1_lo[i]);
    } else if (blk < PR_F2) {                 // fc2_w 128x300 -> 128x384
        int i = (blk - PR_F1) * 256 + t;
        int r = i / KF, c = i - r * KF;
        float v = (c < 300) ? fc2w[(size_t)r * 300 + c] : 0.f;
        split_h(v, f2_hi[i], f2_lo[i]);
    } else if (blk < PR_BC) {                 // bc = [W2_b ; gru_b_hh]
        int i = (blk - PR_F2) * 256 + t;
        bc[i] = (i < 512) ? w2b[i] : bhh[i - 512];
    } else if (blk < PR_BF) {                 // bfc1 padded
        int i = (blk - PR_BC) * 256 + t;
        if (i < KF) bfc1[i] = (i < 300) ? f1b[i] : 0.f;
    }
}

// ================= HMMA fp16 2-pass GEMM =================
// C[M,N] = A[M,K] @ (Bhi+Blo)[N,K]^T + bias ; CTA 64Mx128N, 8 warps 2Mx4N.
#define HG_BUF  40960
#define HG_SMEM 81920
template<int OUT>
__global__ void __launch_bounds__(256) hgemm(
    const __half* __restrict__ A,
    const __half* __restrict__ Bhi, const __half* __restrict__ Blo,
    const float* __restrict__ bias, float* __restrict__ C,
    __half* __restrict__ Ch, int K, int lda, int ldc)
{
    extern __shared__ __align__(128) char sm[];
    const uint32_t smb = smem_u32(sm);
    const int tid = threadIdx.x, wid = tid >> 5, lane = tid & 31;
    const int mb = wid & 1, nw = wid >> 1;
    const int m0 = blockIdx.y * 64, n0 = blockIdx.x * 128;
    const int nk = K >> 6;

    auto prefetch = [&](int kc) {
        uint32_t base = smb + (uint32_t)(kc & 1) * HG_BUF;
        #pragma unroll
        for (int it = 0; it < 2; it++) {
            int idx = tid + it * 256;
            int r = idx >> 3, c = idx & 7;
            uint32_t dst = base + r * 128 + ((uint32_t)(c ^ (r & 7)) << 4);
            cpasync16(dst, A + (size_t)(m0 + r) * lda + kc * 64 + c * 8);
        }
        #pragma unroll
        for (int it = 0; it < 4; it++) {
            int idx = tid + it * 256;
            int r = idx >> 3, c = idx & 7;
            uint32_t dst = base + 8192 + r * 128 + ((uint32_t)(c ^ (r & 7)) << 4);
            size_t go = (size_t)(n0 + r) * K + kc * 64 + c * 8;
            cpasync16(dst,         Bhi + go);
            cpasync16(dst + 16384, Blo + go);
        }
        CP_COMMIT();
    };

    float acc[2][4][4] = {};
    const int aswz = lane & 7;
    prefetch(0);

    for (int kc = 0; kc < nk; kc++) {
        if (kc + 1 < nk) {
            prefetch(kc + 1);
            asm volatile("cp.async.wait_group 1;" ::: "memory");
        } else {
            asm volatile("cp.async.wait_group 0;" ::: "memory");
        }
        __syncthreads();
        uint32_t base = smb + (uint32_t)(kc & 1) * HG_BUF;
        uint32_t aB[2], bB[2];
        #pragma unroll
        for (int f = 0; f < 2; f++) {
            aB[f] = base + (mb * 32 + f * 16 + (lane & 15)) * 128;
            bB[f] = base + 8192 + (nw * 32 + f * 16 + (lane & 15)) * 128;
        }
        #pragma unroll
        for (int ks = 0; ks < 4; ks++) {
            int chunk = ks * 2 + (lane >> 4);
            uint32_t coff = (uint32_t)(chunk ^ aswz) << 4;
            uint32_t ah[2][4], bh[2][4], bl[2][4];
            #pragma unroll
            for (int f = 0; f < 2; f++) {
                ldm_x4(ah[f], aB[f] + coff);
                ldm_x4(bh[f], bB[f] + coff);
                ldm_x4(bl[f], bB[f] + coff + 16384);
            }
            #pragma unroll
            for (int m = 0; m < 2; m++)
                #pragma unroll
                for (int f2 = 0; f2 < 2; f2++)
                    #pragma unroll
                    for (int sel = 0; sel < 2; sel++) {
                        int n8 = f2 * 2 + sel;
                        uint32_t bfh[2] = { bh[f2][sel], bh[f2][sel + 2] };
                        uint32_t bfl[2] = { bl[f2][sel], bl[f2][sel + 2] };
                        mma_h(acc[m][n8], ah[m], bfh);
                        mma_h(acc[m][n8], ah[m], bfl);
                    }
        }
        __syncthreads();
    }

    #pragma unroll
    for (int f = 0; f < 2; f++) {
        int r0 = m0 + mb * 32 + f * 16 + (lane >> 2);
        int r1 = r0 + 8;
        #pragma unroll
        for (int n8 = 0; n8 < 4; n8++) {
            int col = n0 + nw * 32 + n8 * 8 + ((lane & 3) << 1);
            float b0 = bias[col], b1 = bias[col + 1];
            float v00 = acc[f][n8][0] + b0, v01 = acc[f][n8][1] + b1;
            float v10 = acc[f][n8][2] + b0, v11 = acc[f][n8][3] + b1;
            if (OUT == 0) {
                *(float2*)&C[(size_t)r0 * ldc + col] = make_float2(v00, v01);
                *(float2*)&C[(size_t)r1 * ldc + col] = make_float2(v10, v11);
            } else {
                v00 = (v00 > 0.f) ? v00 : 0.01f * v00;
                v01 = (v01 > 0.f) ? v01 : 0.01f * v01;
                v10 = (v10 > 0.f) ? v10 : 0.01f * v10;
                v11 = (v11 > 0.f) ? v11 : 0.01f * v11;
                *(uint32_t*)&Ch[(size_t)r0 * ldc + col] = pack_h2(v00, v01);
                *(uint32_t*)&Ch[(size_t)r1 * ldc + col] = pack_h2(v10, v11);
            }
        }
    }
}

// ================= fused attention: logits + softmax + ctx =================
#define SA       0          // 128 x 1024 B
#define SB       131072     // 2 x (hi 16K + lo 16K)
#define UVW_OFF  196608
#define PART_OFF 200704
#define SW_OFF   202752
#define RED_OFF  203264
#define ATT_SMEM 204288

__global__ void __launch_bounds__(256) attn_fused(
    const float* __restrict__ enc,
    const __half* __restrict__ w1hi, const __half* __restrict__ w1lo,
    const float* __restrict__ W1b, const float* __restrict__ ug,
    const float* __restrict__ Vw, const float* __restrict__ Vb,
    __half* __restrict__ ginh)
{
    extern __shared__ __align__(128) char sm[];
    const uint32_t smb = smem_u32(sm);
    const int tid = threadIdx.x, wid = tid >> 5, lane = tid & 31;
    const int b = blockIdx.x;
    const int mb = wid & 1, nw = wid >> 1;

    // early B prefetch overlaps the A-slab global read
    auto prefetch = [&](int itc) {
        int nt = itc >> 3, kc = itc & 7, buf = itc & 1;
        #pragma unroll
        for (int it2 = 0; it2 < 4; it2++) {
            int idx = tid + it2 * 256;
            int r = idx >> 3, c = idx & 7;
            uint32_t dst = smb + SB + buf * 32768 + r * 128 + ((uint32_t)(c ^ (r & 7)) << 4);
            size_t gofs = (size_t)(nt * 128 + r) * HH + kc * 64 + c * 8;
            cpasync16(dst,         w1hi + gofs);
            cpasync16(dst + 16384, w1lo + gofs);
        }
        CP_COMMIT();
    };
    prefetch(0);

    float2* uvw = (float2*)(sm + UVW_OFF);
    for (int n = tid; n < HH; n += 256)
        uvw[n] = make_float2(ug[(size_t)b * 2048 + n] + W1b[n], Vw[n]);

    // A slab: 128 x 512 fp32 -> fp16, swizzled (row stride 1024 B)
    #pragma unroll 4
    for (int it = 0; it < 32; it++) {
        int idx = tid + it * 256;
        int r = idx >> 6, c = idx & 63;
        const float4* src = (const float4*)(enc + (size_t)(b * SS + r) * HH + c * 8);
        float4 v0 = src[0], v1 = src[1];
        uint4 hv;
        hv.x = pack_h2(v0.x, v0.y); hv.y = pack_h2(v0.z, v0.w);
        hv.z = pack_h2(v1.x, v1.y); hv.w = pack_h2(v1.z, v1.w);
        uint32_t off = (uint32_t)(r * 1024 + ((c ^ (r & 7)) << 4));
        *(uint4*)(sm + SA + off) = hv;
    }
    __syncthreads();

    const int aswz = lane & 7;
    uint32_t aB[4], bB[2];
    #pragma unroll
    for (int f = 0; f < 4; f++)
        aB[f] = smb + SA + (mb * 64 + f * 16 + (lane & 15)) * 1024;
    #pragma unroll
    for (int f2 = 0; f2 < 2; f2++)
        bB[f2] = smb + SB + (nw * 32 + f2 * 16 + (lane & 15)) * 128;

    float acc[4][4][4] = {};
    float rp[8] = {};

    for (int itc = 0; itc < 32; itc++) {
        const int nt = itc >> 3, kc = itc & 7, buf = itc & 1;
        if (itc < 31) {
            prefetch(itc + 1);
            asm volatile("cp.async.wait_group 1;" ::: "memory");
        } else {
            asm volatile("cp.async.wait_group 0;" ::: "memory");
        }
        __syncthreads();

        #pragma unroll
        for (int ks = 0; ks < 4; ks++) {
            int achunk = kc * 8 + ks * 2 + (lane >> 4);
            uint32_t acoff = (uint32_t)(achunk ^ aswz) << 4;
            int bchunk = ks * 2 + (lane >> 4);
            uint32_t bcoff = (uint32_t)(bchunk ^ aswz) << 4;
            uint32_t ah[4][4], bh[2][4], bl[2][4];
            #pragma unroll
            for (int f = 0; f < 4; f++) ldm_x4(ah[f], aB[f] + acoff);
            #pragma unroll
            for (int f2 = 0; f2 < 2; f2++) {
                ldm_x4(bh[f2], bB[f2] + buf * 32768 + bcoff);
                ldm_x4(bl[f2], bB[f2] + buf * 32768 + bcoff + 16384);
            }
            #pragma unroll
            for (int f = 0; f < 4; f++)
                #pragma unroll
                for (int f2 = 0; f2 < 2; f2++)
                    #pragma unroll
                    for (int sel = 0; sel < 2; sel++) {
                        int n8 = f2 * 2 + sel;
                        uint32_t bfh[2] = { bh[f2][sel], bh[f2][sel + 2] };
                        uint32_t bfl[2] = { bl[f2][sel], bl[f2][sel + 2] };
                        mma_h(acc[f][n8], ah[f], bfh);
                        mma_h(acc[f][n8], ah[f], bfl);
                    }
        }
        __syncthreads();

        if (kc == 7) {
            #pragma unroll
            for (int f = 0; f < 4; f++)
                #pragma unroll
                for (int n8 = 0; n8 < 4; n8++) {
                    int n = nt * 128 + nw * 32 + n8 * 8 + ((lane & 3) << 1);
                    float2 u0 = uvw[n], u1 = uvw[n + 1];
                    rp[f * 2]     += tanh_fast(acc[f][n8][0] + u0.x) * u0.y
                                   + tanh_fast(acc[f][n8][1] + u1.x) * u1.y;
                    rp[f * 2 + 1] += tanh_fast(acc[f][n8][2] + u0.x) * u0.y
                                   + tanh_fast(acc[f][n8][3] + u1.x) * u1.y;
                    acc[f][n8][0] = acc[f][n8][1] = acc[f][n8][2] = acc[f][n8][3] = 0.f;
                }
        }
    }

    #pragma unroll
    for (int i = 0; i < 8; i++) {
        rp[i] += __shfl_xor_sync(0xffffffffu, rp[i], 1);
        rp[i] += __shfl_xor_sync(0xffffffffu, rp[i], 2);
    }
    float* part = (float*)(sm + PART_OFF);
    if ((lane & 3) == 0) {
        #pragma unroll
        for (int f = 0; f < 4; f++) {
            int row = mb * 64 + f * 16 + (lane >> 2);
            part[nw * 128 + row]     = rp[f * 2];
            part[nw * 128 + row + 8] = rp[f * 2 + 1];
        }
    }
    __syncthreads();

    // logits + softmax (128 values)
    float* w   = (float*)(sm + SW_OFF);
    float* red = (float*)(sm + RED_OFF);
    float lg = -1e30f;
    if (tid < 128)
        lg = part[tid] + part[128 + tid] + part[256 + tid] + part[384 + tid] + Vb[0];
    red[tid] = lg;
    __syncthreads();
    for (int s = 128; s > 0; s >>= 1) {
        if (tid < s) red[tid] = fmaxf(red[tid], red[tid + s]);
        __syncthreads();
    }
    float mx = red[0];
    __syncthreads();
    float e = (tid < 128) ? __expf(lg - mx) : 0.f;
    red[tid] = e;
    __syncthreads();
    for (int s = 128; s > 0; s >>= 1) {
        if (tid < s) red[tid] += red[tid + s];
        __syncthreads();
    }
    float inv = 1.f / red[0];
    if (tid < 128) w[tid] = e * inv;
    __syncthreads();

    // ctx from resident fp16 slab: thread -> cols (2*tid, 2*tid+1)
    {
        int h0 = tid * 2;
        int chunk = h0 >> 3;
        uint32_t byte_in = (uint32_t)(h0 & 7) * 2;
        float c0 = 0.f, c1 = 0.f;
        #pragma unroll 8
        for (int s = 0; s < SS; s++) {
            float ws = w[s];
            uint32_t addr = (uint32_t)(s * 1024 + (((uint32_t)(chunk ^ (s & 7))) << 4) + byte_in);
            __half2 hv = *(__half2*)(sm + SA + addr);
            float2 f2v = __half22float2(hv);
            c0 = fmaf(ws, f2v.x, c0);
            c1 = fmaf(ws, f2v.y, c1);
        }
        *(uint32_t*)&ginh[(size_t)b * KIH + h0] = pack_h2(c0, c1);
    }
}

// ---------------- embedding gather into gin[:, 512:832] ----------------
__global__ void emb_gather(const int* __restrict__ x,
                           const float* __restrict__ emb_table,
                           __half* __restrict__ ginh)
{
    int i = blockIdx.x * blockDim.x + threadIdx.x;
    if (i >= BB * 320) return;
    int b = i / 320, e = i - b * 320;
    float v = (e < EE) ? emb_table[(size_t)x[b] * EE + e] : 0.f;
    ginh[(size_t)b * KIH + HH + e] = __float2half_rn(v);
}

// ---------------- GRU pointwise (fast-math) ----------------
__global__ void gru_pointwise(const float* __restrict__ gi,
                              const float* __restrict__ ug,
                              const float* __restrict__ h0,
                              float* __restrict__ hout,
                              __half* __restrict__ hnh)
{
    int i = blockIdx.x * blockDim.x + threadIdx.x;
    if (i >= BB * HH) return;
    int b = i >> 9, h = i & 511;
    size_t gib = (size_t)b * H3 + h;
    size_t ghb = (size_t)b * 2048 + 512 + h;
    float i_r = gi[gib], i_z = gi[gib + HH], i_n = gi[gib + 2 * HH];
    float h_r = ug[ghb], h_z = ug[ghb + HH], h_n = ug[ghb + 2 * HH];
    float r = sigmoid_fast(i_r + h_r);
    float z = sigmoid_fast(i_z + h_z);
    float n = tanh_acc(i_n + r * h_n);
    float hn = (1.f - z) * n + z * h0[i];
    hout[i] = hn;
    hnh[i] = __float2half_rn(hn);
}

// ---------------- launch ----------------
extern "C" void kernel_launch(void* const* d_in, const int* in_sizes, int n_in,
                              void* d_out, int out_size)
{
    const int*   x        = (const int*)  d_in[0];
    const float* hidden   = (const float*)d_in[1];
    const float* enc      = (const float*)d_in[2];
    const float* emb_t    = (const float*)d_in[3];
    const float* W1_w     = (const float*)d_in[4];
    const float* W1_b     = (const float*)d_in[5];
    const float* W2_w     = (const float*)d_in[6];
    const float* W2_b     = (const float*)d_in[7];
    const float* V_w      = (const float*)d_in[8];
    const float* V_b      = (const float*)d_in[9];
    const float* gru_w_ih = (const float*)d_in[10];
    const float* gru_w_hh = (const float*)d_in[11];
    const float* gru_b_ih = (const float*)d_in[12];
    // d_in[13] = gru_b_hh (zeros folded via prep)  -- still used below
    const float* gru_b_hh = (const float*)d_in[13];
    const float* fc1_w    = (const float*)d_in[14];
    const float* fc1_b    = (const float*)d_in[15];
    const float* fc2_w    = (const float*)d_in[16];
    const float* fc2_b    = (const float*)d_in[17];

    float* y_out = (float*)d_out;
    float* h_out = y_out + (size_t)BB * VV;

    float *p_ug, *p_gi, *p_bc, *p_bfc1;
    __half *p_hid, *p_wch, *p_wcl, *p_w1h, *p_w1l, *p_wihh, *p_wihl;
    __half *p_gin, *p_hn, *p_f1h, *p_f1l, *p_f2h, *p_f2l, *p_a1;
    cudaGetSymbolAddress((void**)&p_ug, g_ug);
    cudaGetSymbolAddress((void**)&p_gi, g_gi);
    cudaGetSymbolAddress((void**)&p_bc, g_bc);
    cudaGetSymbolAddress((void**)&p_bfc1, g_bfc1);
    cudaGetSymbolAddress((void**)&p_hid, g_hid_h);
    cudaGetSymbolAddress((void**)&p_wch, g_wc_hi);   cudaGetSymbolAddress((void**)&p_wcl, g_wc_lo);
    cudaGetSymbolAddress((void**)&p_w1h, g_w1_hi);   cudaGetSymbolAddress((void**)&p_w1l, g_w1_lo);
    cudaGetSymbolAddress((void**)&p_wihh, g_wih_hi); cudaGetSymbolAddress((void**)&p_wihl, g_wih_lo);
    cudaGetSymbolAddress((void**)&p_gin, g_gin_h);
    cudaGetSymbolAddress((void**)&p_hn, g_hn_h);
    cudaGetSymbolAddress((void**)&p_f1h, g_f1_hi);   cudaGetSymbolAddress((void**)&p_f1l, g_f1_lo);
    cudaGetSymbolAddress((void**)&p_f2h, g_f2_hi);   cudaGetSymbolAddress((void**)&p_f2l, g_f2_lo);
    cudaGetSymbolAddress((void**)&p_a1, g_a1_h);

    cudaFuncSetAttribute(attn_fused, cudaFuncAttributeMaxDynamicSharedMemorySize, ATT_SMEM);
    cudaFuncSetAttribute(hgemm<0>, cudaFuncAttributeMaxDynamicSharedMemorySize, HG_SMEM);
    cudaFuncSetAttribute(hgemm<1>, cudaFuncAttributeMaxDynamicSharedMemorySize, HG_SMEM);

    // launches 1-4: prep (merged)
    prep_w1<<<1024, 256>>>(W1_w, p_w1h, p_w1l);
    prep_wc<<<4096, 256>>>(W2_w, gru_w_hh, p_wch, p_wcl);
    cvt_h<<<4096, 256>>>(hidden, p_hid);
    prep_rest<<<PR_BF, 256>>>(gru_w_ih, fc1_w, fc2_w, W2_b, gru_b_hh, fc1_b,
                              p_wihh, p_wihl, p_f1h, p_f1l, p_f2h, p_f2l, p_bc, p_bfc1);
    // launch 5: ug = h0 @ [W2; gru_w_hh]^T + bias
    hgemm<0><<<dim3(2048 / 128, BB / 64), 256, HG_SMEM>>>(
        p_hid, p_wch, p_wcl, p_bc, p_ug, nullptr, 512, 512, 2048);
    // launch 6 (ncu target): fused attention
    attn_fused<<<BB, 256, ATT_SMEM>>>(enc, p_w1h, p_w1l, W1_b, p_ug, V_w, V_b, p_gin);
    // launch 7: emb
    emb_gather<<<(BB * 320 + 255) / 256, 256>>>(x, emb_t, p_gin);
    // launch 8: gi
    hgemm<0><<<dim3(H3 / 128, BB / 64), 256, HG_SMEM>>>(
        p_gin, p_wihh, p_wihl, gru_b_ih, p_gi, nullptr, KIH, KIH, H3);
    // launch 9: GRU pointwise
    gru_pointwise<<<(BB * HH + 255) / 256, 256>>>(p_gi, p_ug, hidden, h_out, p_hn);
    // launch 10: fc1
    hgemm<1><<<dim3(KF / 128, BB / 64), 256, HG_SMEM>>>(
        p_hn, p_f1h, p_f1l, p_bfc1, nullptr, p_a1, 512, 512, KF);
    // launch 11: fc2
    hgemm<0><<<dim3(VV / 128, BB / 64), 256, HG_SMEM>>>(
        p_a1, p_f2h, p_f2l, fc2_b, y_out, nullptr, KF, KF, VV);
}

// round 12
// speedup vs baseline: 9.2054x; 1.5127x over previous
#include <cuda_runtime.h>
#include <cuda_fp16.h>
#include <math.h>
#include <stdint.h>

// Problem dims
#define BB 2048
#define SS 128
#define VV 128
#define EE 300
#define HH 512
#define H3 1536
#define KIH 832              // padded 812
#define KF  384              // fc1-out / fc2-K padding

// ---------------- scratch (device globals) ----------------
__device__ float  g_ug[BB * 2048];           // [u | gh]
__device__ float  g_gi[BB * H3];
__device__ __half g_hid_h[BB * HH];
__device__ __half g_wc_hi[2048 * HH], g_wc_lo[2048 * HH];   // [W2; gru_w_hh]
__device__ __half g_w1_hi[HH * HH];
__device__ __half g_wih_hi[H3 * KIH], g_wih_lo[H3 * KIH];
__device__ __half g_gin_h[BB * KIH];
__device__ __half g_hn_h[BB * HH];
__device__ __half g_f1_hi[KF * HH],  g_f1_lo[KF * HH];
__device__ __half g_f2_hi[VV * KF],  g_f2_lo[VV * KF];
__device__ __half g_a1_h[BB * KF];
__device__ float  g_bc[2048];
__device__ float  g_bfc1[KF];

// ================= helpers =================
__device__ __forceinline__ uint32_t smem_u32(const void* p) {
    uint32_t a;
    asm("{ .reg .u64 t; cvta.to.shared.u64 t, %1; cvt.u32.u64 %0, t; }" : "=r"(a) : "l"(p));
    return a;
}
__device__ __forceinline__ void ldm_x4(uint32_t* r, uint32_t addr) {
    asm volatile("ldmatrix.sync.aligned.m8n8.x4.shared.b16 {%0,%1,%2,%3}, [%4];"
        : "=r"(r[0]), "=r"(r[1]), "=r"(r[2]), "=r"(r[3]) : "r"(addr));
}
__device__ __forceinline__ void mma_h(float* c, const uint32_t* a, const uint32_t* b) {
    asm volatile("mma.sync.aligned.m16n8k16.row.col.f32.f16.f16.f32 "
        "{%0,%1,%2,%3}, {%4,%5,%6,%7}, {%8,%9}, {%0,%1,%2,%3};"
        : "+f"(c[0]), "+f"(c[1]), "+f"(c[2]), "+f"(c[3])
        : "r"(a[0]), "r"(a[1]), "r"(a[2]), "r"(a[3]), "r"(b[0]), "r"(b[1]));
}
__device__ __forceinline__ void cpasync16(uint32_t dst, const void* src) {
    asm volatile("cp.async.cg.shared.global [%0], [%1], 16;" :: "r"(dst), "l"(src) : "memory");
}
#define CP_COMMIT() asm volatile("cp.async.commit_group;" ::: "memory")
#define CP_WAIT0()  asm volatile("cp.async.wait_group 0;" ::: "memory")

__device__ __forceinline__ uint32_t pack_h2(float a, float b) {
    __half2 t = __floats2half2_rn(a, b);
    return *(uint32_t*)&t;
}
__device__ __forceinline__ float tanh_fast(float x) {
    float y;
    asm("tanh.approx.f32 %0, %1;" : "=f"(y) : "f"(x));
    return y;
}
__device__ __forceinline__ float tanh_acc(float x) {
    x = fminf(fmaxf(x, -15.f), 15.f);
    float e = __expf(2.f * x);
    return __fdividef(e - 1.f, e + 1.f);
}
__device__ __forceinline__ float sigmoid_fast(float x) {
    return __fdividef(1.f, 1.f + __expf(-x));
}
__device__ __forceinline__ void split_h(float v, __half& h, __half& l) {
    h = __float2half_rn(v);
    l = __float2half_rn(v - __half2float(h));
}

// ================= prep kernels =================
__global__ void prep_w1(const float* __restrict__ w1, __half* __restrict__ hi) {
    int i = blockIdx.x * 256 + threadIdx.x;          // 1024 blocks
    hi[i] = __float2half_rn(w1[i]);
}
__global__ void prep_wc(const float* __restrict__ w2, const float* __restrict__ whh,
                        __half* __restrict__ hi, __half* __restrict__ lo) {
    int i = blockIdx.x * 256 + threadIdx.x;          // 4096 blocks
    int r = i >> 9;
    float v = (r < 512) ? w2[i] : whh[i - 512 * 512];
    split_h(v, hi[i], lo[i]);
}
__global__ void cvt_h(const float* __restrict__ src, __half* __restrict__ dst) {
    int i = blockIdx.x * 256 + threadIdx.x;          // 4096 blocks
    dst[i] = __float2half_rn(src[i]);
}
#define PR_WIH 4992
#define PR_F1  (PR_WIH + 768)
#define PR_F2  (PR_F1 + 192)
#define PR_BC  (PR_F2 + 8)
#define PR_BF  (PR_BC + 2)
__global__ void prep_rest(const float* __restrict__ wih,
                          const float* __restrict__ fc1w, const float* __restrict__ fc2w,
                          const float* __restrict__ w2b, const float* __restrict__ bhh,
                          const float* __restrict__ f1b,
                          __half* __restrict__ wih_hi, __half* __restrict__ wih_lo,
                          __half* __restrict__ f1_hi,  __half* __restrict__ f1_lo,
                          __half* __restrict__ f2_hi,  __half* __restrict__ f2_lo,
                          float* __restrict__ bc, float* __restrict__ bfc1) {
    int blk = blockIdx.x;
    int t = threadIdx.x;
    if (blk < PR_WIH) {
        int i = blk * 256 + t;
        int r = i / KIH, c = i - r * KIH;
        float v = (c < 812) ? wih[(size_t)r * 812 + c] : 0.f;
        split_h(v, wih_hi[i], wih_lo[i]);
    } else if (blk < PR_F1) {
        int i = (blk - PR_WIH) * 256 + t;
        int r = i >> 9;
        float v = (r < 300) ? fc1w[i] : 0.f;
        split_h(v, f1_hi[i], f1_lo[i]);
    } else if (blk < PR_F2) {
        int i = (blk - PR_F1) * 256 + t;
        int r = i / KF, c = i - r * KF;
        float v = (c < 300) ? fc2w[(size_t)r * 300 + c] : 0.f;
        split_h(v, f2_hi[i], f2_lo[i]);
    } else if (blk < PR_BC) {
        int i = (blk - PR_F2) * 256 + t;
        bc[i] = (i < 512) ? w2b[i] : bhh[i - 512];
    } else if (blk < PR_BF) {
        int i = (blk - PR_BC) * 256 + t;
        if (i < KF) bfc1[i] = (i < 300) ? f1b[i] : 0.f;
    }
}

// ================= HMMA fp16 2-pass GEMM (single-sync mainloop) =================
#define HG_BUF  40960
#define HG_SMEM 81920
template<int OUT>
__global__ void __launch_bounds__(256) hgemm(
    const __half* __restrict__ A,
    const __half* __restrict__ Bhi, const __half* __restrict__ Blo,
    const float* __restrict__ bias, float* __restrict__ C,
    __half* __restrict__ Ch, int K, int lda, int ldc)
{
    extern __shared__ __align__(128) char sm[];
    const uint32_t smb = smem_u32(sm);
    const int tid = threadIdx.x, wid = tid >> 5, lane = tid & 31;
    const int mb = wid & 1, nw = wid >> 1;
    const int m0 = blockIdx.y * 64, n0 = blockIdx.x * 128;
    const int nk = K >> 6;

    auto prefetch = [&](int kc) {
        uint32_t base = smb + (uint32_t)(kc & 1) * HG_BUF;
        #pragma unroll
        for (int it = 0; it < 2; it++) {
            int idx = tid + it * 256;
            int r = idx >> 3, c = idx & 7;
            uint32_t dst = base + r * 128 + ((uint32_t)(c ^ (r & 7)) << 4);
            cpasync16(dst, A + (size_t)(m0 + r) * lda + kc * 64 + c * 8);
        }
        #pragma unroll
        for (int it = 0; it < 4; it++) {
            int idx = tid + it * 256;
            int r = idx >> 3, c = idx & 7;
            uint32_t dst = base + 8192 + r * 128 + ((uint32_t)(c ^ (r & 7)) << 4);
            size_t go = (size_t)(n0 + r) * K + kc * 64 + c * 8;
            cpasync16(dst,         Bhi + go);
            cpasync16(dst + 16384, Blo + go);
        }
        CP_COMMIT();
    };

    float acc[2][4][4] = {};
    const int aswz = lane & 7;
    prefetch(0);

    for (int kc = 0; kc < nk; kc++) {
        CP_WAIT0();
        __syncthreads();               // data ready + all warps done with other buffer
        if (kc + 1 < nk) prefetch(kc + 1);
        uint32_t base = smb + (uint32_t)(kc & 1) * HG_BUF;
        uint32_t aB[2], bB[2];
        #pragma unroll
        for (int f = 0; f < 2; f++) {
            aB[f] = base + (mb * 32 + f * 16 + (lane & 15)) * 128;
            bB[f] = base + 8192 + (nw * 32 + f * 16 + (lane & 15)) * 128;
        }
        #pragma unroll
        for (int ks = 0; ks < 4; ks++) {
            int chunk = ks * 2 + (lane >> 4);
            uint32_t coff = (uint32_t)(chunk ^ aswz) << 4;
            uint32_t ah[2][4], bh[2][4], bl[2][4];
            #pragma unroll
            for (int f = 0; f < 2; f++) {
                ldm_x4(ah[f], aB[f] + coff);
                ldm_x4(bh[f], bB[f] + coff);
                ldm_x4(bl[f], bB[f] + coff + 16384);
            }
            #pragma unroll
            for (int m = 0; m < 2; m++)
                #pragma unroll
                for (int f2 = 0; f2 < 2; f2++)
                    #pragma unroll
                    for (int sel = 0; sel < 2; sel++) {
                        int n8 = f2 * 2 + sel;
                        uint32_t bfh[2] = { bh[f2][sel], bh[f2][sel + 2] };
                        uint32_t bfl[2] = { bl[f2][sel], bl[f2][sel + 2] };
                        mma_h(acc[m][n8], ah[m], bfh);
                        mma_h(acc[m][n8], ah[m], bfl);
                    }
        }
    }

    #pragma unroll
    for (int f = 0; f < 2; f++) {
        int r0 = m0 + mb * 32 + f * 16 + (lane >> 2);
        int r1 = r0 + 8;
        #pragma unroll
        for (int n8 = 0; n8 < 4; n8++) {
            int col = n0 + nw * 32 + n8 * 8 + ((lane & 3) << 1);
            float b0 = bias[col], b1 = bias[col + 1];
            float v00 = acc[f][n8][0] + b0, v01 = acc[f][n8][1] + b1;
            float v10 = acc[f][n8][2] + b0, v11 = acc[f][n8][3] + b1;
            if (OUT == 0) {
                *(float2*)&C[(size_t)r0 * ldc + col] = make_float2(v00, v01);
                *(float2*)&C[(size_t)r1 * ldc + col] = make_float2(v10, v11);
            } else {
                v00 = (v00 > 0.f) ? v00 : 0.01f * v00;
                v01 = (v01 > 0.f) ? v01 : 0.01f * v01;
                v10 = (v10 > 0.f) ? v10 : 0.01f * v10;
                v11 = (v11 > 0.f) ? v11 : 0.01f * v11;
                *(uint32_t*)&Ch[(size_t)r0 * ldc + col] = pack_h2(v00, v01);
                *(uint32_t*)&Ch[(size_t)r1 * ldc + col] = pack_h2(v10, v11);
            }
        }
    }
}

// ================= fused attention: logits + softmax + ctx =================
// Single-pass fp16 (A enc fp16, B = W1 hi only). CTA = 128 rows = one b.
#define SA       0                    // 128 x 1024 B = 131072
#define SB       131072               // 2 bufs x 16384 (hi only)
#define UVW_OFF  163840               // float2[512]
#define PART_OFF 167936               // float[512]
#define SW_OFF   169984               // float[128]
#define RED_OFF  170496               // float[256]
#define ATT_SMEM 171520

__global__ void __launch_bounds__(256) attn_fused(
    const float* __restrict__ enc,
    const __half* __restrict__ w1hi,
    const float* __restrict__ W1b, const float* __restrict__ ug,
    const float* __restrict__ Vw, const float* __restrict__ Vb,
    __half* __restrict__ ginh)
{
    extern __shared__ __align__(128) char sm[];
    const uint32_t smb = smem_u32(sm);
    const int tid = threadIdx.x, wid = tid >> 5, lane = tid & 31;
    const int b = blockIdx.x;
    const int mb = wid & 1, nw = wid >> 1;

    auto prefetch = [&](int itc) {
        int nt = itc >> 3, kc = itc & 7, buf = itc & 1;
        #pragma unroll
        for (int it2 = 0; it2 < 2; it2++) {
            int idx = tid + it2 * 256;
            int r = idx >> 2, c = idx & 3;            // 128 rows x 4 chunks of 16B? -> 64 cols = 8 chunks
            // 128 rows x 8 chunks = 1024 iters over 512 threads-slots: use 2 iters of 512? we have 256 threads
            (void)r; (void)c;
        }
        // 128 rows x 8 chunks (16B) = 1024 loads over 256 threads = 4 iters
        #pragma unroll
        for (int it2 = 0; it2 < 4; it2++) {
            int idx = tid + it2 * 256;
            int r = idx >> 3, c = idx & 7;
            uint32_t dst = smb + SB + buf * 16384 + r * 128 + ((uint32_t)(c ^ (r & 7)) << 4);
            cpasync16(dst, w1hi + (size_t)(nt * 128 + r) * HH + kc * 64 + c * 8);
        }
        CP_COMMIT();
    };
    prefetch(0);

    float2* uvw = (float2*)(sm + UVW_OFF);
    for (int n = tid; n < HH; n += 256)
        uvw[n] = make_float2(ug[(size_t)b * 2048 + n] + W1b[n], Vw[n]);

    // A slab: 128 x 512 fp32 -> fp16, swizzled (row stride 1024 B)
    #pragma unroll 4
    for (int it = 0; it < 32; it++) {
        int idx = tid + it * 256;
        int r = idx >> 6, c = idx & 63;
        const float4* src = (const float4*)(enc + (size_t)(b * SS + r) * HH + c * 8);
        float4 v0 = src[0], v1 = src[1];
        uint4 hv;
        hv.x = pack_h2(v0.x, v0.y); hv.y = pack_h2(v0.z, v0.w);
        hv.z = pack_h2(v1.x, v1.y); hv.w = pack_h2(v1.z, v1.w);
        uint32_t off = (uint32_t)(r * 1024 + ((c ^ (r & 7)) << 4));
        *(uint4*)(sm + SA + off) = hv;
    }

    const int aswz = lane & 7;
    uint32_t aB[4], bB[2];
    #pragma unroll
    for (int f = 0; f < 4; f++)
        aB[f] = smb + SA + (mb * 64 + f * 16 + (lane & 15)) * 1024;
    #pragma unroll
    for (int f2 = 0; f2 < 2; f2++)
        bB[f2] = smb + SB + (nw * 32 + f2 * 16 + (lane & 15)) * 128;

    float acc[4][4][4] = {};
    float rp[8] = {};

    for (int itc = 0; itc < 32; itc++) {
        const int nt = itc >> 3, kc = itc & 7, buf = itc & 1;
        CP_WAIT0();
        __syncthreads();               // B ready + A slab ready (itc 0) + buffer-reuse safety
        if (itc < 31) prefetch(itc + 1);

        #pragma unroll
        for (int ks = 0; ks < 4; ks++) {
            int achunk = kc * 8 + ks * 2 + (lane >> 4);
            uint32_t acoff = (uint32_t)(achunk ^ aswz) << 4;
            int bchunk = ks * 2 + (lane >> 4);
            uint32_t bcoff = (uint32_t)(bchunk ^ aswz) << 4;
            uint32_t ah[4][4], bh[2][4];
            #pragma unroll
            for (int f = 0; f < 4; f++) ldm_x4(ah[f], aB[f] + acoff);
            #pragma unroll
            for (int f2 = 0; f2 < 2; f2++)
                ldm_x4(bh[f2], bB[f2] + buf * 16384 + bcoff);
            #pragma unroll
            for (int f = 0; f < 4; f++)
                #pragma unroll
                for (int f2 = 0; f2 < 2; f2++)
                    #pragma unroll
                    for (int sel = 0; sel < 2; sel++) {
                        int n8 = f2 * 2 + sel;
                        uint32_t bfh[2] = { bh[f2][sel], bh[f2][sel + 2] };
                        mma_h(acc[f][n8], ah[f], bfh);
                    }
        }

        if (kc == 7) {
            #pragma unroll
            for (int f = 0; f < 4; f++)
                #pragma unroll
                for (int n8 = 0; n8 < 4; n8++) {
                    int n = nt * 128 + nw * 32 + n8 * 8 + ((lane & 3) << 1);
                    float2 u0 = uvw[n], u1 = uvw[n + 1];
                    rp[f * 2]     += tanh_fast(acc[f][n8][0] + u0.x) * u0.y
                                   + tanh_fast(acc[f][n8][1] + u1.x) * u1.y;
                    rp[f * 2 + 1] += tanh_fast(acc[f][n8][2] + u0.x) * u0.y
                                   + tanh_fast(acc[f][n8][3] + u1.x) * u1.y;
                    acc[f][n8][0] = acc[f][n8][1] = acc[f][n8][2] = acc[f][n8][3] = 0.f;
                }
        }
    }

    #pragma unroll
    for (int i = 0; i < 8; i++) {
        rp[i] += __shfl_xor_sync(0xffffffffu, rp[i], 1);
        rp[i] += __shfl_xor_sync(0xffffffffu, rp[i], 2);
    }
    float* part = (float*)(sm + PART_OFF);
    if ((lane & 3) == 0) {
        #pragma unroll
        for (int f = 0; f < 4; f++) {
            int row = mb * 64 + f * 16 + (lane >> 2);
            part[nw * 128 + row]     = rp[f * 2];
            part[nw * 128 + row + 8] = rp[f * 2 + 1];
        }
    }
    __syncthreads();

    // logits + softmax
    float* w   = (float*)(sm + SW_OFF);
    float* red = (float*)(sm + RED_OFF);
    float lg = -1e30f;
    if (tid < 128)
        lg = part[tid] + part[128 + tid] + part[256 + tid] + part[384 + tid] + Vb[0];
    red[tid] = lg;
    __syncthreads();
    for (int s = 128; s > 0; s >>= 1) {
        if (tid < s) red[tid] = fmaxf(red[tid], red[tid + s]);
        __syncthreads();
    }
    float mx = red[0];
    __syncthreads();
    float e = (tid < 128) ? __expf(lg - mx) : 0.f;
    red[tid] = e;
    __syncthreads();
    for (int s = 128; s > 0; s >>= 1) {
        if (tid < s) red[tid] += red[tid + s];
        __syncthreads();
    }
    float inv = 1.f / red[0];
    if (tid < 128) w[tid] = e * inv;
    __syncthreads();

    // ctx from resident fp16 slab
    {
        int h0 = tid * 2;
        int chunk = h0 >> 3;
        uint32_t byte_in = (uint32_t)(h0 & 7) * 2;
        float c0 = 0.f, c1 = 0.f;
        #pragma unroll 8
        for (int s = 0; s < SS; s++) {
            float ws = w[s];
            uint32_t addr = (uint32_t)(s * 1024 + (((uint32_t)(chunk ^ (s & 7))) << 4) + byte_in);
            __half2 hv = *(__half2*)(sm + SA + addr);
            float2 f2v = __half22float2(hv);
            c0 = fmaf(ws, f2v.x, c0);
            c1 = fmaf(ws, f2v.y, c1);
        }
        *(uint32_t*)&ginh[(size_t)b * KIH + h0] = pack_h2(c0, c1);
    }
}

// ---------------- embedding gather ----------------
__global__ void emb_gather(const int* __restrict__ x,
                           const float* __restrict__ emb_table,
                           __half* __restrict__ ginh)
{
    int i = blockIdx.x * blockDim.x + threadIdx.x;
    if (i >= BB * 320) return;
    int b = i / 320, e = i - b * 320;
    float v = (e < EE) ? emb_table[(size_t)x[b] * EE + e] : 0.f;
    ginh[(size_t)b * KIH + HH + e] = __float2half_rn(v);
}

// ---------------- GRU pointwise ----------------
__global__ void gru_pointwise(const float* __restrict__ gi,
                              const float* __restrict__ ug,
                              const float* __restrict__ h0,
                              float* __restrict__ hout,
                              __half* __restrict__ hnh)
{
    int i = blockIdx.x * blockDim.x + threadIdx.x;
    if (i >= BB * HH) return;
    int b = i >> 9, h = i & 511;
    size_t gib = (size_t)b * H3 + h;
    size_t ghb = (size_t)b * 2048 + 512 + h;
    float i_r = gi[gib], i_z = gi[gib + HH], i_n = gi[gib + 2 * HH];
    float h_r = ug[ghb], h_z = ug[ghb + HH], h_n = ug[ghb + 2 * HH];
    float r = sigmoid_fast(i_r + h_r);
    float z = sigmoid_fast(i_z + h_z);
    float n = tanh_acc(i_n + r * h_n);
    float hn = (1.f - z) * n + z * h0[i];
    hout[i] = hn;
    hnh[i] = __float2half_rn(hn);
}

// ---------------- launch ----------------
extern "C" void kernel_launch(void* const* d_in, const int* in_sizes, int n_in,
                              void* d_out, int out_size)
{
    const int*   x        = (const int*)  d_in[0];
    const float* hidden   = (const float*)d_in[1];
    const float* enc      = (const float*)d_in[2];
    const float* emb_t    = (const float*)d_in[3];
    const float* W1_w     = (const float*)d_in[4];
    const float* W1_b     = (const float*)d_in[5];
    const float* W2_w     = (const float*)d_in[6];
    const float* W2_b     = (const float*)d_in[7];
    const float* V_w      = (const float*)d_in[8];
    const float* V_b      = (const float*)d_in[9];
    const float* gru_w_ih = (const float*)d_in[10];
    const float* gru_w_hh = (const float*)d_in[11];
    const float* gru_b_ih = (const float*)d_in[12];
    const float* gru_b_hh = (const float*)d_in[13];
    const float* fc1_w    = (const float*)d_in[14];
    const float* fc1_b    = (const float*)d_in[15];
    const float* fc2_w    = (const float*)d_in[16];
    const float* fc2_b    = (const float*)d_in[17];

    float* y_out = (float*)d_out;
    float* h_out = y_out + (size_t)BB * VV;

    float *p_ug, *p_gi, *p_bc, *p_bfc1;
    __half *p_hid, *p_wch, *p_wcl, *p_w1h, *p_wihh, *p_wihl;
    __half *p_gin, *p_hn, *p_f1h, *p_f1l, *p_f2h, *p_f2l, *p_a1;
    cudaGetSymbolAddress((void**)&p_ug, g_ug);
    cudaGetSymbolAddress((void**)&p_gi, g_gi);
    cudaGetSymbolAddress((void**)&p_bc, g_bc);
    cudaGetSymbolAddress((void**)&p_bfc1, g_bfc1);
    cudaGetSymbolAddress((void**)&p_hid, g_hid_h);
    cudaGetSymbolAddress((void**)&p_wch, g_wc_hi);   cudaGetSymbolAddress((void**)&p_wcl, g_wc_lo);
    cudaGetSymbolAddress((void**)&p_w1h, g_w1_hi);
    cudaGetSymbolAddress((void**)&p_wihh, g_wih_hi); cudaGetSymbolAddress((void**)&p_wihl, g_wih_lo);
    cudaGetSymbolAddress((void**)&p_gin, g_gin_h);
    cudaGetSymbolAddress((void**)&p_hn, g_hn_h);
    cudaGetSymbolAddress((void**)&p_f1h, g_f1_hi);   cudaGetSymbolAddress((void**)&p_f1l, g_f1_lo);
    cudaGetSymbolAddress((void**)&p_f2h, g_f2_hi);   cudaGetSymbolAddress((void**)&p_f2l, g_f2_lo);
    cudaGetSymbolAddress((void**)&p_a1, g_a1_h);

    cudaFuncSetAttribute(attn_fused, cudaFuncAttributeMaxDynamicSharedMemorySize, ATT_SMEM);
    cudaFuncSetAttribute(hgemm<0>, cudaFuncAttributeMaxDynamicSharedMemorySize, HG_SMEM);
    cudaFuncSetAttribute(hgemm<1>, cudaFuncAttributeMaxDynamicSharedMemorySize, HG_SMEM);

    // prep
    prep_w1<<<1024, 256>>>(W1_w, p_w1h);
    prep_wc<<<4096, 256>>>(W2_w, gru_w_hh, p_wch, p_wcl);
    cvt_h<<<4096, 256>>>(hidden, p_hid);
    prep_rest<<<PR_BF, 256>>>(gru_w_ih, fc1_w, fc2_w, W2_b, gru_b_hh, fc1_b,
                              p_wihh, p_wihl, p_f1h, p_f1l, p_f2h, p_f2l, p_bc, p_bfc1);
    // ug = h0 @ [W2; gru_w_hh]^T + bias
    hgemm<0><<<dim3(2048 / 128, BB / 64), 256, HG_SMEM>>>(
        p_hid, p_wch, p_wcl, p_bc, p_ug, nullptr, 512, 512, 2048);
    // fused attention
    attn_fused<<<BB, 256, ATT_SMEM>>>(enc, p_w1h, W1_b, p_ug, V_w, V_b, p_gin);
    // emb
    emb_gather<<<(BB * 320 + 255) / 256, 256>>>(x, emb_t, p_gin);
    // gi
    hgemm<0><<<dim3(H3 / 128, BB / 64), 256, HG_SMEM>>>(
        p_gin, p_wihh, p_wihl, gru_b_ih, p_gi, nullptr, KIH, KIH, H3);
    // GRU pointwise
    gru_pointwise<<<(BB * HH + 255) / 256, 256>>>(p_gi, p_ug, hidden, h_out, p_hn);
    // fc1
    hgemm<1><<<dim3(KF / 128, BB / 64), 256, HG_SMEM>>>(
        p_hn, p_f1h, p_f1l, p_bfc1, nullptr, p_a1, 512, 512, KF);
    // fc2
    hgemm<0><<<dim3(VV / 128, BB / 64), 256, HG_SMEM>>>(
        p_a1, p_f2h, p_f2l, fc2_b, y_out, nullptr, KF, KF, VV);
}

// round 13
// speedup vs baseline: 9.5886x; 1.0416x over previous
#include <cuda_runtime.h>
#include <cuda_fp16.h>
#include <math.h>
#include <stdint.h>

// Problem dims
#define BB 2048
#define SS 128
#define VV 128
#define EE 300
#define HH 512
#define H3 1536
#define KIH 832              // padded 812
#define KF  384              // fc1-out / fc2-K padding

// ---------------- scratch (device globals) ----------------
__device__ float  g_ug[BB * 2048];           // [u | gh]
__device__ float  g_gi[BB * H3];
__device__ __half g_hid_h[BB * HH];
__device__ __half g_wc_h[2048 * HH];         // [W2; gru_w_hh]
__device__ __half g_w1_h[HH * HH];
__device__ __half g_wih_h[H3 * KIH];
__device__ __half g_gin_h[BB * KIH];
__device__ __half g_hn_h[BB * HH];
__device__ __half g_f1_h[KF * HH];
__device__ __half g_f2_h[VV * KF];
__device__ __half g_a1_h[BB * KF];
__device__ float  g_bc[2048];
__device__ float  g_bfc1[KF];

// ================= helpers =================
__device__ __forceinline__ uint32_t smem_u32(const void* p) {
    uint32_t a;
    asm("{ .reg .u64 t; cvta.to.shared.u64 t, %1; cvt.u32.u64 %0, t; }" : "=r"(a) : "l"(p));
    return a;
}
__device__ __forceinline__ void ldm_x4(uint32_t* r, uint32_t addr) {
    asm volatile("ldmatrix.sync.aligned.m8n8.x4.shared.b16 {%0,%1,%2,%3}, [%4];"
        : "=r"(r[0]), "=r"(r[1]), "=r"(r[2]), "=r"(r[3]) : "r"(addr));
}
__device__ __forceinline__ void mma_h(float* c, const uint32_t* a, const uint32_t* b) {
    asm volatile("mma.sync.aligned.m16n8k16.row.col.f32.f16.f16.f32 "
        "{%0,%1,%2,%3}, {%4,%5,%6,%7}, {%8,%9}, {%0,%1,%2,%3};"
        : "+f"(c[0]), "+f"(c[1]), "+f"(c[2]), "+f"(c[3])
        : "r"(a[0]), "r"(a[1]), "r"(a[2]), "r"(a[3]), "r"(b[0]), "r"(b[1]));
}
__device__ __forceinline__ void cpasync16(uint32_t dst, const void* src) {
    asm volatile("cp.async.cg.shared.global [%0], [%1], 16;" :: "r"(dst), "l"(src) : "memory");
}
#define CP_COMMIT() asm volatile("cp.async.commit_group;" ::: "memory")
#define CP_WAIT0()  asm volatile("cp.async.wait_group 0;" ::: "memory")

__device__ __forceinline__ uint32_t pack_h2(float a, float b) {
    __half2 t = __floats2half2_rn(a, b);
    return *(uint32_t*)&t;
}
__device__ __forceinline__ float tanh_fast(float x) {
    float y;
    asm("tanh.approx.f32 %0, %1;" : "=f"(y) : "f"(x));
    return y;
}
__device__ __forceinline__ float tanh_acc(float x) {
    x = fminf(fmaxf(x, -15.f), 15.f);
    float e = __expf(2.f * x);
    return __fdividef(e - 1.f, e + 1.f);
}
__device__ __forceinline__ float sigmoid_fast(float x) {
    return __fdividef(1.f, 1.f + __expf(-x));
}

// ================= single merged prep kernel =================
#define PB_W1  1024
#define PB_WC  (PB_W1 + 4096)
#define PB_HID (PB_W1 + 8192)
#define PB_WIH (PB_HID + 4992)
#define PB_F1  (PB_WIH + 768)
#define PB_F2  (PB_F1 + 192)
#define PB_BC  (PB_F2 + 8)
#define PB_BF  (PB_BC + 2)
__global__ void prep_all(const float* __restrict__ w1, const float* __restrict__ w2,
                         const float* __restrict__ whh, const float* __restrict__ hid,
                         const float* __restrict__ wih,
                         const float* __restrict__ fc1w, const float* __restrict__ fc2w,
                         const float* __restrict__ w2b, const float* __restrict__ bhh,
                         const float* __restrict__ f1b,
                         __half* __restrict__ w1_h, __half* __restrict__ wc_h,
                         __half* __restrict__ hid_h, __half* __restrict__ wih_h,
                         __half* __restrict__ f1_h, __half* __restrict__ f2_h,
                         float* __restrict__ bc, float* __restrict__ bfc1)
{
    int blk = blockIdx.x, t = threadIdx.x;
    if (blk < PB_W1) {
        int i = blk * 256 + t;
        w1_h[i] = __float2half_rn(w1[i]);
    } else if (blk < PB_WC) {
        int i = (blk - PB_W1) * 256 + t;
        float v = (i < 512 * 512) ? w2[i] : whh[i - 512 * 512];
        wc_h[i] = __float2half_rn(v);
    } else if (blk < PB_HID) {
        int i = (blk - PB_WC) * 256 + t;
        hid_h[i] = __float2half_rn(hid[i]);
    } else if (blk < PB_WIH) {
        int i = (blk - PB_HID) * 256 + t;
        int r = i / KIH, c = i - r * KIH;
        wih_h[i] = __float2half_rn((c < 812) ? wih[(size_t)r * 812 + c] : 0.f);
    } else if (blk < PB_F1) {
        int i = (blk - PB_WIH) * 256 + t;
        int r = i >> 9;
        f1_h[i] = __float2half_rn((r < 300) ? fc1w[i] : 0.f);
    } else if (blk < PB_F2) {
        int i = (blk - PB_F1) * 256 + t;
        int r = i / KF, c = i - r * KF;
        f2_h[i] = __float2half_rn((c < 300) ? fc2w[(size_t)r * 300 + c] : 0.f);
    } else if (blk < PB_BC) {
        int i = (blk - PB_F2) * 256 + t;
        bc[i] = (i < 512) ? w2b[i] : bhh[i - 512];
    } else if (blk < PB_BF) {
        int i = (blk - PB_BC) * 256 + t;
        if (i < KF) bfc1[i] = (i < 300) ? f1b[i] : 0.f;
    }
}

// ================= HMMA fp16 single-pass GEMM =================
// C[M,N] = A[M,K] @ B[N,K]^T + bias ; CTA 64Mx128N, 8 warps 2Mx4N.
#define HG_BUF  24576            // A 8K | B 16K
#define HG_SMEM 49152
template<int OUT>
__global__ void __launch_bounds__(256) hgemm(
    const __half* __restrict__ A, const __half* __restrict__ B,
    const float* __restrict__ bias, float* __restrict__ C,
    __half* __restrict__ Ch, int K, int lda, int ldc)
{
    extern __shared__ __align__(128) char sm[];
    const uint32_t smb = smem_u32(sm);
    const int tid = threadIdx.x, wid = tid >> 5, lane = tid & 31;
    const int mb = wid & 1, nw = wid >> 1;
    const int m0 = blockIdx.y * 64, n0 = blockIdx.x * 128;
    const int nk = K >> 6;

    auto prefetch = [&](int kc) {
        uint32_t base = smb + (uint32_t)(kc & 1) * HG_BUF;
        #pragma unroll
        for (int it = 0; it < 2; it++) {
            int idx = tid + it * 256;
            int r = idx >> 3, c = idx & 7;
            uint32_t dst = base + r * 128 + ((uint32_t)(c ^ (r & 7)) << 4);
            cpasync16(dst, A + (size_t)(m0 + r) * lda + kc * 64 + c * 8);
        }
        #pragma unroll
        for (int it = 0; it < 4; it++) {
            int idx = tid + it * 256;
            int r = idx >> 3, c = idx & 7;
            uint32_t dst = base + 8192 + r * 128 + ((uint32_t)(c ^ (r & 7)) << 4);
            cpasync16(dst, B + (size_t)(n0 + r) * K + kc * 64 + c * 8);
        }
        CP_COMMIT();
    };

    float acc[2][4][4] = {};
    const int aswz = lane & 7;
    prefetch(0);

    for (int kc = 0; kc < nk; kc++) {
        CP_WAIT0();
        __syncthreads();
        if (kc + 1 < nk) prefetch(kc + 1);
        uint32_t base = smb + (uint32_t)(kc & 1) * HG_BUF;
        uint32_t aB[2], bB[2];
        #pragma unroll
        for (int f = 0; f < 2; f++) {
            aB[f] = base + (mb * 32 + f * 16 + (lane & 15)) * 128;
            bB[f] = base + 8192 + (nw * 32 + f * 16 + (lane & 15)) * 128;
        }
        #pragma unroll
        for (int ks = 0; ks < 4; ks++) {
            int chunk = ks * 2 + (lane >> 4);
            uint32_t coff = (uint32_t)(chunk ^ aswz) << 4;
            uint32_t ah[2][4], bh[2][4];
            #pragma unroll
            for (int f = 0; f < 2; f++) {
                ldm_x4(ah[f], aB[f] + coff);
                ldm_x4(bh[f], bB[f] + coff);
            }
            #pragma unroll
            for (int m = 0; m < 2; m++)
                #pragma unroll
                for (int f2 = 0; f2 < 2; f2++)
                    #pragma unroll
                    for (int sel = 0; sel < 2; sel++) {
                        uint32_t bf[2] = { bh[f2][sel], bh[f2][sel + 2] };
                        mma_h(acc[m][f2 * 2 + sel], ah[m], bf);
                    }
        }
    }

    #pragma unroll
    for (int f = 0; f < 2; f++) {
        int r0 = m0 + mb * 32 + f * 16 + (lane >> 2);
        int r1 = r0 + 8;
        #pragma unroll
        for (int n8 = 0; n8 < 4; n8++) {
            int col = n0 + nw * 32 + n8 * 8 + ((lane & 3) << 1);
            float b0 = bias[col], b1 = bias[col + 1];
            float v00 = acc[f][n8][0] + b0, v01 = acc[f][n8][1] + b1;
            float v10 = acc[f][n8][2] + b0, v11 = acc[f][n8][3] + b1;
            if (OUT == 0) {
                *(float2*)&C[(size_t)r0 * ldc + col] = make_float2(v00, v01);
                *(float2*)&C[(size_t)r1 * ldc + col] = make_float2(v10, v11);
            } else {
                v00 = (v00 > 0.f) ? v00 : 0.01f * v00;
                v01 = (v01 > 0.f) ? v01 : 0.01f * v01;
                v10 = (v10 > 0.f) ? v10 : 0.01f * v10;
                v11 = (v11 > 0.f) ? v11 : 0.01f * v11;
                *(uint32_t*)&Ch[(size_t)r0 * ldc + col] = pack_h2(v00, v01);
                *(uint32_t*)&Ch[(size_t)r1 * ldc + col] = pack_h2(v10, v11);
            }
        }
    }
}

// ================= fused attention: logits + softmax + ctx + emb =================
#define SA       0                    // 128 x 1024 B = 131072
#define SB       131072               // 2 bufs x 16384
#define UVW_OFF  163840               // float2[512]
#define PART_OFF 167936               // float[512]
#define SW_OFF   169984               // float[128]
#define RED_OFF  170496               // float[256]
#define ATT_SMEM 171520

__global__ void __launch_bounds__(256) attn_fused(
    const float* __restrict__ enc,
    const __half* __restrict__ w1h,
    const float* __restrict__ W1b, const float* __restrict__ ug,
    const float* __restrict__ Vw, const float* __restrict__ Vb,
    const int* __restrict__ x, const float* __restrict__ emb_table,
    __half* __restrict__ ginh)
{
    extern __shared__ __align__(128) char sm[];
    const uint32_t smb = smem_u32(sm);
    const int tid = threadIdx.x, wid = tid >> 5, lane = tid & 31;
    const int b = blockIdx.x;
    const int mb = wid & 1, nw = wid >> 1;

    auto prefetch = [&](int itc) {
        int nt = itc >> 3, kc = itc & 7, buf = itc & 1;
        #pragma unroll
        for (int it2 = 0; it2 < 4; it2++) {
            int idx = tid + it2 * 256;
            int r = idx >> 3, c = idx & 7;
            uint32_t dst = smb + SB + buf * 16384 + r * 128 + ((uint32_t)(c ^ (r & 7)) << 4);
            cpasync16(dst, w1h + (size_t)(nt * 128 + r) * HH + kc * 64 + c * 8);
        }
        CP_COMMIT();
    };
    prefetch(0);

    float2* uvw = (float2*)(sm + UVW_OFF);
    for (int n = tid; n < HH; n += 256)
        uvw[n] = make_float2(ug[(size_t)b * 2048 + n] + W1b[n], Vw[n]);

    // A slab: 128 x 512 fp32 -> fp16, swizzled (row stride 1024 B)
    #pragma unroll 4
    for (int it = 0; it < 32; it++) {
        int idx = tid + it * 256;
        int r = idx >> 6, c = idx & 63;
        const float4* src = (const float4*)(enc + (size_t)(b * SS + r) * HH + c * 8);
        float4 v0 = src[0], v1 = src[1];
        uint4 hv;
        hv.x = pack_h2(v0.x, v0.y); hv.y = pack_h2(v0.z, v0.w);
        hv.z = pack_h2(v1.x, v1.y); hv.w = pack_h2(v1.z, v1.w);
        uint32_t off = (uint32_t)(r * 1024 + ((c ^ (r & 7)) << 4));
        *(uint4*)(sm + SA + off) = hv;
    }

    const int aswz = lane & 7;
    uint32_t aB[4], bB[2];
    #pragma unroll
    for (int f = 0; f < 4; f++)
        aB[f] = smb + SA + (mb * 64 + f * 16 + (lane & 15)) * 1024;
    #pragma unroll
    for (int f2 = 0; f2 < 2; f2++)
        bB[f2] = smb + SB + (nw * 32 + f2 * 16 + (lane & 15)) * 128;

    float acc[4][4][4] = {};
    float rp[8] = {};

    for (int itc = 0; itc < 32; itc++) {
        const int nt = itc >> 3, kc = itc & 7, buf = itc & 1;
        CP_WAIT0();
        __syncthreads();
        if (itc < 31) prefetch(itc + 1);

        #pragma unroll
        for (int ks = 0; ks < 4; ks++) {
            int achunk = kc * 8 + ks * 2 + (lane >> 4);
            uint32_t acoff = (uint32_t)(achunk ^ aswz) << 4;
            int bchunk = ks * 2 + (lane >> 4);
            uint32_t bcoff = (uint32_t)(bchunk ^ aswz) << 4;
            uint32_t ah[4][4], bh[2][4];
            #pragma unroll
            for (int f = 0; f < 4; f++) ldm_x4(ah[f], aB[f] + acoff);
            #pragma unroll
            for (int f2 = 0; f2 < 2; f2++)
                ldm_x4(bh[f2], bB[f2] + buf * 16384 + bcoff);
            #pragma unroll
            for (int f = 0; f < 4; f++)
                #pragma unroll
                for (int f2 = 0; f2 < 2; f2++)
                    #pragma unroll
                    for (int sel = 0; sel < 2; sel++) {
                        uint32_t bf[2] = { bh[f2][sel], bh[f2][sel + 2] };
                        mma_h(acc[f][f2 * 2 + sel], ah[f], bf);
                    }
        }

        if (kc == 7) {
            #pragma unroll
            for (int f = 0; f < 4; f++)
                #pragma unroll
                for (int n8 = 0; n8 < 4; n8++) {
                    int n = nt * 128 + nw * 32 + n8 * 8 + ((lane & 3) << 1);
                    float2 u0 = uvw[n], u1 = uvw[n + 1];
                    rp[f * 2]     += tanh_fast(acc[f][n8][0] + u0.x) * u0.y
                                   + tanh_fast(acc[f][n8][1] + u1.x) * u1.y;
                    rp[f * 2 + 1] += tanh_fast(acc[f][n8][2] + u0.x) * u0.y
                                   + tanh_fast(acc[f][n8][3] + u1.x) * u1.y;
                    acc[f][n8][0] = acc[f][n8][1] = acc[f][n8][2] = acc[f][n8][3] = 0.f;
                }
        }
    }

    #pragma unroll
    for (int i = 0; i < 8; i++) {
        rp[i] += __shfl_xor_sync(0xffffffffu, rp[i], 1);
        rp[i] += __shfl_xor_sync(0xffffffffu, rp[i], 2);
    }
    float* part = (float*)(sm + PART_OFF);
    if ((lane & 3) == 0) {
        #pragma unroll
        for (int f = 0; f < 4; f++) {
            int row = mb * 64 + f * 16 + (lane >> 2);
            part[nw * 128 + row]     = rp[f * 2];
            part[nw * 128 + row + 8] = rp[f * 2 + 1];
        }
    }
    __syncthreads();

    // logits + softmax
    float* w   = (float*)(sm + SW_OFF);
    float* red = (float*)(sm + RED_OFF);
    float lg = -1e30f;
    if (tid < 128)
        lg = part[tid] + part[128 + tid] + part[256 + tid] + part[384 + tid] + Vb[0];
    red[tid] = lg;
    __syncthreads();
    for (int s = 128; s > 0; s >>= 1) {
        if (tid < s) red[tid] = fmaxf(red[tid], red[tid + s]);
        __syncthreads();
    }
    float mx = red[0];
    __syncthreads();
    float e = (tid < 128) ? __expf(lg - mx) : 0.f;
    red[tid] = e;
    __syncthreads();
    for (int s = 128; s > 0; s >>= 1) {
        if (tid < s) red[tid] += red[tid + s];
        __syncthreads();
    }
    float inv = 1.f / red[0];
    if (tid < 128) w[tid] = e * inv;
    __syncthreads();

    // ctx from resident fp16 slab -> gin[:, 0:512]
    {
        int h0 = tid * 2;
        int chunk = h0 >> 3;
        uint32_t byte_in = (uint32_t)(h0 & 7) * 2;
        float c0 = 0.f, c1 = 0.f;
        #pragma unroll 8
        for (int s = 0; s < SS; s++) {
            float ws = w[s];
            uint32_t addr = (uint32_t)(s * 1024 + (((uint32_t)(chunk ^ (s & 7))) << 4) + byte_in);
            __half2 hv = *(__half2*)(sm + SA + addr);
            float2 f2v = __half22float2(hv);
            c0 = fmaf(ws, f2v.x, c0);
            c1 = fmaf(ws, f2v.y, c1);
        }
        *(uint32_t*)&ginh[(size_t)b * KIH + h0] = pack_h2(c0, c1);
    }

    // emb gather -> gin[:, 512:832] (300 real + 20 pad)
    {
        int tok = x[b];
        const float* erow = emb_table + (size_t)tok * EE;
        for (int e2 = tid; e2 < 320; e2 += 256) {
            float v = (e2 < EE) ? erow[e2] : 0.f;
            ginh[(size_t)b * KIH + HH + e2] = __float2half_rn(v);
        }
    }
}

// ---------------- GRU pointwise ----------------
__global__ void gru_pointwise(const float* __restrict__ gi,
                              const float* __restrict__ ug,
                              const float* __restrict__ h0,
                              float* __restrict__ hout,
                              __half* __restrict__ hnh)
{
    int i = blockIdx.x * blockDim.x + threadIdx.x;
    if (i >= BB * HH) return;
    int b = i >> 9, h = i & 511;
    size_t gib = (size_t)b * H3 + h;
    size_t ghb = (size_t)b * 2048 + 512 + h;
    float i_r = gi[gib], i_z = gi[gib + HH], i_n = gi[gib + 2 * HH];
    float h_r = ug[ghb], h_z = ug[ghb + HH], h_n = ug[ghb + 2 * HH];
    float r = sigmoid_fast(i_r + h_r);
    float z = sigmoid_fast(i_z + h_z);
    float n = tanh_acc(i_n + r * h_n);
    float hn = (1.f - z) * n + z * h0[i];
    hout[i] = hn;
    hnh[i] = __float2half_rn(hn);
}

// ---------------- launch ----------------
extern "C" void kernel_launch(void* const* d_in, const int* in_sizes, int n_in,
                              void* d_out, int out_size)
{
    const int*   x        = (const int*)  d_in[0];
    const float* hidden   = (const float*)d_in[1];
    const float* enc      = (const float*)d_in[2];
    const float* emb_t    = (const float*)d_in[3];
    const float* W1_w     = (const float*)d_in[4];
    const float* W1_b     = (const float*)d_in[5];
    const float* W2_w     = (const float*)d_in[6];
    const float* W2_b     = (const float*)d_in[7];
    const float* V_w      = (const float*)d_in[8];
    const float* V_b      = (const float*)d_in[9];
    const float* gru_w_ih = (const float*)d_in[10];
    const float* gru_w_hh = (const float*)d_in[11];
    const float* gru_b_ih = (const float*)d_in[12];
    const float* gru_b_hh = (const float*)d_in[13];
    const float* fc1_w    = (const float*)d_in[14];
    const float* fc1_b    = (const float*)d_in[15];
    const float* fc2_w    = (const float*)d_in[16];
    const float* fc2_b    = (const float*)d_in[17];

    float* y_out = (float*)d_out;
    float* h_out = y_out + (size_t)BB * VV;

    float *p_ug, *p_gi, *p_bc, *p_bfc1;
    __half *p_hid, *p_wc, *p_w1, *p_wih, *p_gin, *p_hn, *p_f1, *p_f2, *p_a1;
    cudaGetSymbolAddress((void**)&p_ug, g_ug);
    cudaGetSymbolAddress((void**)&p_gi, g_gi);
    cudaGetSymbolAddress((void**)&p_bc, g_bc);
    cudaGetSymbolAddress((void**)&p_bfc1, g_bfc1);
    cudaGetSymbolAddress((void**)&p_hid, g_hid_h);
    cudaGetSymbolAddress((void**)&p_wc, g_wc_h);
    cudaGetSymbolAddress((void**)&p_w1, g_w1_h);
    cudaGetSymbolAddress((void**)&p_wih, g_wih_h);
    cudaGetSymbolAddress((void**)&p_gin, g_gin_h);
    cudaGetSymbolAddress((void**)&p_hn, g_hn_h);
    cudaGetSymbolAddress((void**)&p_f1, g_f1_h);
    cudaGetSymbolAddress((void**)&p_f2, g_f2_h);
    cudaGetSymbolAddress((void**)&p_a1, g_a1_h);

    cudaFuncSetAttribute(attn_fused, cudaFuncAttributeMaxDynamicSharedMemorySize, ATT_SMEM);
    cudaFuncSetAttribute(hgemm<0>, cudaFuncAttributeMaxDynamicSharedMemorySize, HG_SMEM);
    cudaFuncSetAttribute(hgemm<1>, cudaFuncAttributeMaxDynamicSharedMemorySize, HG_SMEM);

    // 1: merged prep
    prep_all<<<PB_BF, 256>>>(W1_w, W2_w, gru_w_hh, hidden, gru_w_ih, fc1_w, fc2_w,
                             W2_b, gru_b_hh, fc1_b,
                             p_w1, p_wc, p_hid, p_wih, p_f1, p_f2, p_bc, p_bfc1);
    // 2: ug = h0 @ [W2; gru_w_hh]^T + bias
    hgemm<0><<<dim3(2048 / 128, BB / 64), 256, HG_SMEM>>>(
        p_hid, p_wc, p_bc, p_ug, nullptr, 512, 512, 2048);
    // 3: fused attention (+softmax+ctx+emb)
    attn_fused<<<BB, 256, ATT_SMEM>>>(enc, p_w1, W1_b, p_ug, V_w, V_b, x, emb_t, p_gin);
    // 4: gi = gin @ gru_w_ih^T + gru_b_ih
    hgemm<0><<<dim3(H3 / 128, BB / 64), 256, HG_SMEM>>>(
        p_gin, p_wih, gru_b_ih, p_gi, nullptr, KIH, KIH, H3);
    // 5: GRU pointwise
    gru_pointwise<<<(BB * HH + 255) / 256, 256>>>(p_gi, p_ug, hidden, h_out, p_hn);
    // 6: fc1
    hgemm<1><<<dim3(KF / 128, BB / 64), 256, HG_SMEM>>>(
        p_hn, p_f1, p_bfc1, nullptr, p_a1, 512, 512, KF);
    // 7: fc2
    hgemm<0><<<dim3(VV / 128, BB / 64), 256, HG_SMEM>>>(
        p_a1, p_f2, fc2_b, y_out, nullptr, KF, KF, VV);
}